// round 7
// baseline (speedup 1.0000x reference)
#include <cuda_runtime.h>
#include <cuda_fp16.h>
#include <math.h>
#include <stdint.h>

#define B_  512
#define S_  200
#define H_  256
#define K_  16
#define ROWS (B_*S_)          // 102400
#define TM  64                // rows per CTA
#define NBLK (ROWS/TM)        // 1600

// smem layout in 32-bit words; all fp16 data, 2 fp16 per word
#define ASTW  132             // A row stride (words); banks 4g+tq distinct
#define CBSTW 20              // W-chunk row stride (words); banks 20g+tq distinct
#define A_WORDS  (64*ASTW)                // 8448
#define BC_OFF   A_WORDS
#define BC_ONE   (256*CBSTW)              // 5120
#define W3_OFF   (BC_OFF + 2*BC_ONE)      // 18688
#define W3STW 132
#define SM_WORDS (W3_OFF + 16*W3STW)      // 20800
#define SM_BYTES (SM_WORDS*4)             // 83200

// scratch
__device__ float    g_A[ROWS * K_];          // masked K-softmax logits
__device__ uint32_t g_Wh[2 * 32768];         // W1,W2 fp16 [l][c8][n256][kl32]
__device__ uint32_t g_Wh3[16 * 128];         // W3 fp16 [n16][k256]

__device__ __forceinline__ uint32_t smem_u32(const void* p) {
    uint32_t a;
    asm("{ .reg .u64 t; cvta.to.shared.u64 t, %1; cvt.u32.u64 %0, t; }"
        : "=r"(a) : "l"(p));
    return a;
}
__device__ __forceinline__ uint32_t pack_h2(float lo, float hi) {
    const __half2 h = __floats2half2_rn(lo, hi);
    return *(const uint32_t*)&h;
}
__device__ __forceinline__ void mma16(float c[4], const uint32_t a[4],
                                      uint32_t b0, uint32_t b1) {
    asm("mma.sync.aligned.m16n8k16.row.col.f32.f16.f16.f32 "
        "{%0,%1,%2,%3}, {%4,%5,%6,%7}, {%8,%9}, {%0,%1,%2,%3};"
        : "+f"(c[0]), "+f"(c[1]), "+f"(c[2]), "+f"(c[3])
        : "r"(a[0]), "r"(a[1]), "r"(a[2]), "r"(a[3]), "r"(b0), "r"(b1));
}
__device__ __forceinline__ void cpasync16(uint32_t dst, const void* src) {
    asm volatile("cp.async.cg.shared.global [%0], [%1], 16;" :: "r"(dst), "l"(src));
}
#define CP_COMMIT() asm volatile("cp.async.commit_group;" ::: "memory")
#define CP_WAIT0()  asm volatile("cp.async.wait_group 0;" ::: "memory")

// ---------------------------------------------------------------------------
// Prep: weights -> fp16 chunk-linear layouts
// g_Wh fp16 idx = ((l*8 + c)*256 + n)*32 + kl  holds W[l][c*32+kl][n]
// g_Wh3 fp16 idx = n*256 + k                   holds W3[k][n]
// ---------------------------------------------------------------------------
__global__ void prep_kernel(const float* __restrict__ W1,
                            const float* __restrict__ W2,
                            const float* __restrict__ W3)
{
    const int i = blockIdx.x * 256 + threadIdx.x;   // one 16B line each
    if (i < 16384) {
        const int kl8 = i & 3;
        const int n   = (i >> 2) & 255;
        const int c   = (i >> 10) & 7;
        const int l   = i >> 13;
        const float* W = l ? W2 : W1;
        const int kbase = c * 32 + kl8 * 8;
        uint4 o;
        o.x = pack_h2(W[(size_t)(kbase+0)*H_ + n], W[(size_t)(kbase+1)*H_ + n]);
        o.y = pack_h2(W[(size_t)(kbase+2)*H_ + n], W[(size_t)(kbase+3)*H_ + n]);
        o.z = pack_h2(W[(size_t)(kbase+4)*H_ + n], W[(size_t)(kbase+5)*H_ + n]);
        o.w = pack_h2(W[(size_t)(kbase+6)*H_ + n], W[(size_t)(kbase+7)*H_ + n]);
        *(uint4*)&g_Wh[(size_t)i * 4] = o;
    } else if (i < 16384 + 512) {
        const int j  = i - 16384;
        const int n  = j >> 5;
        const int k8 = (j & 31) * 8;
        uint4 o;
        o.x = pack_h2(W3[(size_t)(k8+0)*K_ + n], W3[(size_t)(k8+1)*K_ + n]);
        o.y = pack_h2(W3[(size_t)(k8+2)*K_ + n], W3[(size_t)(k8+3)*K_ + n]);
        o.z = pack_h2(W3[(size_t)(k8+4)*K_ + n], W3[(size_t)(k8+5)*K_ + n]);
        o.w = pack_h2(W3[(size_t)(k8+6)*K_ + n], W3[(size_t)(k8+7)*K_ + n]);
        *(uint4*)&g_Wh3[(size_t)j * 4] = o;
    }
}

// ---------------------------------------------------------------------------
// Kernel 1: fp16 mma.sync MLP, cp.async double-buffered K=32 W chunks,
// 2 CTAs/SM. grid = 1600, block = 256 (8 warps; warp grid 2(M) x 4(N))
// ---------------------------------------------------------------------------
__device__ __forceinline__ void prefetch_chunk(uint32_t sb, int tid,
                                               int layer, int cc, int buf) {
    // chunk: 256 n x 32 kl fp16 = 16 words per n-row
    const uint32_t* src = g_Wh + (size_t)(layer * 8 + cc) * 4096 + tid * 16;
    const uint32_t  dst = sb + (uint32_t)(BC_OFF + buf * BC_ONE + tid * CBSTW) * 4;
    #pragma unroll
    for (int j = 0; j < 4; j++) cpasync16(dst + j * 16, src + j * 4);
}
__device__ __forceinline__ void prefetch_w3(uint32_t sb, int tid) {
    #pragma unroll
    for (int q = 0; q < 2; q++) {
        const int i = tid * 2 + q;
        const int n = i >> 5, kk = i & 31;
        cpasync16(sb + (uint32_t)(W3_OFF + n * W3STW + kk * 4) * 4,
                  g_Wh3 + (size_t)i * 4);
    }
}

__global__ __launch_bounds__(256, 2)
void mlp_softk_kernel(const float* __restrict__ X,
                      const int*   __restrict__ mask,
                      const float* __restrict__ b1,
                      const float* __restrict__ b2)
{
    extern __shared__ uint32_t smu[];
    const uint32_t sb = smem_u32(smu);
    const int tid  = threadIdx.x;
    const int wid  = tid >> 5;
    const int lane = tid & 31;
    const int g    = lane >> 2;
    const int tq   = lane & 3;
    const int row0 = blockIdx.x * TM;

    prefetch_chunk(sb, tid, 0, 0, 0);
    CP_COMMIT();

    // X tile -> A (fp16). 64 rows x 64 float4 = 4096 lines, 16 iters.
    #pragma unroll 4
    for (int it = 0; it < 16; it++) {
        const int idx = tid + it * 256;
        const int r = idx >> 6, c4 = (idx & 63) * 4;
        const float4 v = __ldg((const float4*)(X + (size_t)(row0 + r) * H_ + c4));
        uint2 o;
        o.x = pack_h2(v.x, v.y);
        o.y = pack_h2(v.z, v.w);
        *(uint2*)&smu[r * ASTW + (c4 >> 1)] = o;
    }

    const int wm = wid & 1;        // M block: rows wm*32 .. +31
    const int wn = wid >> 1;       // N block: cols wn*64 .. +63

    #pragma unroll 1
    for (int layer = 0; layer < 2; layer++) {
        const float* bg = layer ? b2 : b1;

        float acc[2][8][4];
        #pragma unroll
        for (int mt = 0; mt < 2; mt++)
            #pragma unroll
            for (int n8 = 0; n8 < 8; n8++)
                #pragma unroll
                for (int i = 0; i < 4; i++) acc[mt][n8][i] = 0.0f;

        #pragma unroll 1
        for (int cc = 0; cc < 8; cc++) {
            CP_WAIT0();
            __syncthreads();     // chunk cc landed; mma reads of cc-1 done

            if (layer == 1 && cc == 7) prefetch_w3(sb, tid);
            else {
                const int nl = (cc == 7) ? 1 : layer;
                const int nc = (cc == 7) ? 0 : cc + 1;
                prefetch_chunk(sb, tid, nl, nc, (cc + 1) & 1);
            }
            CP_COMMIT();

            const uint32_t* Bb = smu + BC_OFF + (cc & 1) * BC_ONE;
            #pragma unroll
            for (int ks = 0; ks < 2; ks++) {               // k-step of 16
                const int kw  = (cc * 32 + ks * 16) >> 1;  // word col in A
                const int klw = ks * 8;                    // word col in B chunk
                uint32_t a[2][4];
                #pragma unroll
                for (int mt = 0; mt < 2; mt++) {
                    const int r = wm * 32 + mt * 16 + g;
                    a[mt][0] = smu[(r    ) * ASTW + kw + tq];
                    a[mt][1] = smu[(r + 8) * ASTW + kw + tq];
                    a[mt][2] = smu[(r    ) * ASTW + kw + tq + 4];
                    a[mt][3] = smu[(r + 8) * ASTW + kw + tq + 4];
                }
                #pragma unroll
                for (int n8 = 0; n8 < 8; n8++) {
                    const int n = wn * 64 + n8 * 8 + g;
                    const uint32_t b0 = Bb[n * CBSTW + klw + tq];
                    const uint32_t b1v = Bb[n * CBSTW + klw + tq + 4];
                    mma16(acc[0][n8], a[0], b0, b1v);
                    mma16(acc[1][n8], a[1], b0, b1v);
                }
            }
        }
        __syncthreads();   // all mma reads of A done -> safe to overwrite A

        // epilogue: bias + relu -> fp16 -> A
        #pragma unroll
        for (int mt = 0; mt < 2; mt++) {
            const int r = wm * 32 + mt * 16 + g;
            #pragma unroll
            for (int n8 = 0; n8 < 8; n8++) {
                const int c = wn * 64 + n8 * 8 + 2 * tq;
                const float2 bb = *(const float2*)&bg[c];
                smu[(r    ) * ASTW + (c >> 1)] =
                    pack_h2(fmaxf(acc[mt][n8][0] + bb.x, 0.f),
                            fmaxf(acc[mt][n8][1] + bb.y, 0.f));
                smu[(r + 8) * ASTW + (c >> 1)] =
                    pack_h2(fmaxf(acc[mt][n8][2] + bb.x, 0.f),
                            fmaxf(acc[mt][n8][3] + bb.y, 0.f));
            }
        }
    }

    CP_WAIT0();
    __syncthreads();     // W3 in smem; layer-2 epilogue visible

    // ---- layer 3: logits = h2 @ W3 (warps 0-3, 16 rows each) ----
    if (wid < 4) {
        float acc3[2][4];
        #pragma unroll
        for (int n8 = 0; n8 < 2; n8++)
            #pragma unroll
            for (int i = 0; i < 4; i++) acc3[n8][i] = 0.0f;

        const uint32_t* Bu3 = smu + W3_OFF;
        const int r = wid * 16 + g;
        #pragma unroll 4
        for (int ks = 0; ks < 16; ks++) {
            const int kw = ks * 8;
            uint32_t a[4];
            a[0] = smu[(r    ) * ASTW + kw + tq];
            a[1] = smu[(r + 8) * ASTW + kw + tq];
            a[2] = smu[(r    ) * ASTW + kw + tq + 4];
            a[3] = smu[(r + 8) * ASTW + kw + tq + 4];
            #pragma unroll
            for (int n8 = 0; n8 < 2; n8++) {
                const uint32_t b0 = Bu3[(n8 * 8 + g) * W3STW + kw + tq];
                const uint32_t b1v = Bu3[(n8 * 8 + g) * W3STW + kw + tq + 4];
                mma16(acc3[n8], a, b0, b1v);
            }
        }

        // softmax over K=16 per row, mask, /4, store
        #pragma unroll
        for (int p = 0; p < 2; p++) {
            const int row = row0 + wid * 16 + g + p * 8;
            float v0 = acc3[0][2 * p], v1 = acc3[0][2 * p + 1];
            float v2 = acc3[1][2 * p], v3 = acc3[1][2 * p + 1];
            float m = fmaxf(fmaxf(v0, v1), fmaxf(v2, v3));
            m = fmaxf(m, __shfl_xor_sync(0xffffffffu, m, 1));
            m = fmaxf(m, __shfl_xor_sync(0xffffffffu, m, 2));
            const float e0 = expf(v0 - m), e1 = expf(v1 - m);
            const float e2 = expf(v2 - m), e3 = expf(v3 - m);
            float ssum = e0 + e1 + e2 + e3;
            ssum += __shfl_xor_sync(0xffffffffu, ssum, 1);
            ssum += __shfl_xor_sync(0xffffffffu, ssum, 2);
            const float inv = 0.25f / ssum;             // includes /sqrt(K)=/4
            const bool mk = (mask[row] != 0);
            float2 oa, ob;
            oa.x = mk ? e0 * inv : -2500.0f;            // -10000/4
            oa.y = mk ? e1 * inv : -2500.0f;
            ob.x = mk ? e2 * inv : -2500.0f;
            ob.y = mk ? e3 * inv : -2500.0f;
            *(float2*)&g_A[(size_t)row * K_ + 2 * tq]     = oa;
            *(float2*)&g_A[(size_t)row * K_ + 8 + 2 * tq] = ob;
        }
    }
}

// ---------------------------------------------------------------------------
// Kernel 2: softmax over S per (b,k), * time factor, out[b,k,h] = sum_s X*D
// grid = (512, 2); f32x2 packed FMA. (round-3 version, measured 54.6us)
// ---------------------------------------------------------------------------
__device__ __forceinline__ void fma2(unsigned long long& a,
                                     unsigned long long x, unsigned long long d) {
    asm("fma.rn.f32x2 %0, %1, %2, %0;" : "+l"(a) : "l"(x), "l"(d));
}

__global__ __launch_bounds__(128, 8)
void softs_out_kernel(const float* __restrict__ X,
                      const float* __restrict__ tf,
                      float*       __restrict__ out)
{
    __shared__ __align__(16) float As[S_ * K_];   // 12.8 KB
    __shared__ float Tf[S_];
    __shared__ float Mk[K_], Ik[K_];

    const int b   = blockIdx.x;
    const int hb  = blockIdx.y;
    const int tid = threadIdx.x;

    for (int idx = tid; idx < S_ * K_; idx += 128)
        As[idx] = g_A[(size_t)b * S_ * K_ + idx];
    for (int idx = tid; idx < S_; idx += 128)
        Tf[idx] = tf[b * S_ + idx];
    __syncthreads();

    const int warp = tid >> 5, lane = tid & 31;
    for (int k = warp; k < K_; k += 4) {
        float m = -1e30f;
        for (int s = lane; s < S_; s += 32) m = fmaxf(m, As[s * K_ + k]);
        #pragma unroll
        for (int o = 16; o; o >>= 1) m = fmaxf(m, __shfl_xor_sync(0xffffffffu, m, o));
        float ssum = 0.0f;
        for (int s = lane; s < S_; s += 32) ssum += expf(As[s * K_ + k] - m);
        #pragma unroll
        for (int o = 16; o; o >>= 1) ssum += __shfl_xor_sync(0xffffffffu, ssum, o);
        if (lane == 0) { Mk[k] = m; Ik[k] = 1.0f / ssum; }
    }
    __syncthreads();

    for (int idx = tid; idx < S_ * K_; idx += 128) {
        const int s = idx >> 4, k = idx & 15;
        As[idx] = expf(As[idx] - Mk[k]) * Ik[k] * Tf[s];
    }
    __syncthreads();

    const int h = hb * 128 + tid;
    unsigned long long acc[8];
    #pragma unroll
    for (int i = 0; i < 8; i++) acc[i] = 0ull;

    const float* Xb = X + (size_t)b * S_ * H_ + h;
    #pragma unroll 4
    for (int s = 0; s < S_; s++) {
        const float xv = __ldg(Xb + (size_t)s * H_);
        unsigned long long xv2;
        asm("mov.b64 %0, {%1, %1};" : "=l"(xv2) : "f"(xv));
        const unsigned long long* d = (const unsigned long long*)&As[s * K_];
        #pragma unroll
        for (int i = 0; i < 8; i++) fma2(acc[i], xv2, d[i]);
    }

    float* ob = out + (size_t)b * K_ * H_ + h;
    #pragma unroll
    for (int i = 0; i < 8; i++) {
        float lo, hi;
        asm("mov.b64 {%0, %1}, %2;" : "=f"(lo), "=f"(hi) : "l"(acc[i]));
        ob[(size_t)(2 * i)     * H_] = lo;
        ob[(size_t)(2 * i + 1) * H_] = hi;
    }
}

// ---------------------------------------------------------------------------
extern "C" void kernel_launch(void* const* d_in, const int* in_sizes, int n_in,
                              void* d_out, int out_size)
{
    const float* X    = (const float*)d_in[0];   // (B,S,H)
    const int*   mask = (const int*)  d_in[1];   // (B,S,1)
    const float* tf   = (const float*)d_in[2];   // (B,S,1)
    const float* W1   = (const float*)d_in[3];
    const float* b1   = (const float*)d_in[4];
    const float* W2   = (const float*)d_in[5];
    const float* b2   = (const float*)d_in[6];
    const float* W3   = (const float*)d_in[7];
    float* out = (float*)d_out;                  // (B,K,H)

    cudaFuncSetAttribute(mlp_softk_kernel,
                         cudaFuncAttributeMaxDynamicSharedMemorySize, SM_BYTES);

    prep_kernel<<<66, 256>>>(W1, W2, W3);
    mlp_softk_kernel<<<NBLK, 256, SM_BYTES>>>(X, mask, b1, b2);
    softs_out_kernel<<<dim3(B_, 2), 128>>>(X, tf, out);
}

// round 8
// speedup vs baseline: 1.0490x; 1.0490x over previous
#include <cuda_runtime.h>
#include <cuda_fp16.h>
#include <math.h>
#include <stdint.h>

#define B_  512
#define S_  200
#define H_  256
#define K_  16
#define ROWS (B_*S_)          // 102400
#define TM  128               // rows per CTA
#define NBLK (ROWS/TM)        // 800

// smem layout in 32-bit words; all fp16 data, 2 fp16 per word
#define ASTW  132             // A row stride (words) = 264 fp16; 132 % 32 == 4
#define CBSTW 36              // W-chunk row stride (words) = 72 fp16; 36 % 32 == 4
#define A_WORDS  (128*ASTW)               // 16896
#define BC_OFF   A_WORDS
#define BC_ONE   (256*CBSTW)              // 9216
#define W3_OFF   (BC_OFF + 2*BC_ONE)      // 35328
#define W3STW 132
#define SM_WORDS (W3_OFF + 16*W3STW)      // 37440
#define SM_BYTES (SM_WORDS*4)             // 149760

// scratch
__device__ float    g_A[ROWS * K_];          // masked K-softmax logits
__device__ uint32_t g_Wh[2 * 32768];         // W1,W2 fp16 [l][c4][n256][kl64]
__device__ uint32_t g_Wh3[16 * 128];         // W3 fp16 [n16][k256]

__device__ __forceinline__ uint32_t smem_u32(const void* p) {
    uint32_t a;
    asm("{ .reg .u64 t; cvta.to.shared.u64 t, %1; cvt.u32.u64 %0, t; }"
        : "=r"(a) : "l"(p));
    return a;
}
__device__ __forceinline__ uint32_t pack_h2(float lo, float hi) {
    const __half2 h = __floats2half2_rn(lo, hi);
    return *(const uint32_t*)&h;
}
__device__ __forceinline__ void mma16(float c[4], const uint32_t a[4],
                                      uint32_t b0, uint32_t b1) {
    asm("mma.sync.aligned.m16n8k16.row.col.f32.f16.f16.f32 "
        "{%0,%1,%2,%3}, {%4,%5,%6,%7}, {%8,%9}, {%0,%1,%2,%3};"
        : "+f"(c[0]), "+f"(c[1]), "+f"(c[2]), "+f"(c[3])
        : "r"(a[0]), "r"(a[1]), "r"(a[2]), "r"(a[3]), "r"(b0), "r"(b1));
}
__device__ __forceinline__ void ldsm_x4(uint32_t& r0, uint32_t& r1,
                                        uint32_t& r2, uint32_t& r3, uint32_t addr) {
    asm volatile("ldmatrix.sync.aligned.m8n8.x4.shared.b16 {%0,%1,%2,%3}, [%4];"
                 : "=r"(r0), "=r"(r1), "=r"(r2), "=r"(r3) : "r"(addr));
}
__device__ __forceinline__ void cpasync16(uint32_t dst, const void* src) {
    asm volatile("cp.async.cg.shared.global [%0], [%1], 16;" :: "r"(dst), "l"(src));
}
#define CP_COMMIT() asm volatile("cp.async.commit_group;" ::: "memory")
#define CP_WAIT0()  asm volatile("cp.async.wait_group 0;" ::: "memory")

// ---------------------------------------------------------------------------
// Prep: weights -> fp16 chunk-linear layouts
// g_Wh fp16 idx = ((l*4 + c)*256 + n)*64 + kl  holds W[l][c*64+kl][n]
// g_Wh3 fp16 idx = n*256 + k                   holds W3[k][n]
// ---------------------------------------------------------------------------
__global__ void prep_kernel(const float* __restrict__ W1,
                            const float* __restrict__ W2,
                            const float* __restrict__ W3)
{
    const int i = blockIdx.x * 256 + threadIdx.x;   // one 16B line each
    if (i < 16384) {
        const int kl8 = i & 7;
        const int n   = (i >> 3) & 255;
        const int c   = (i >> 11) & 3;
        const int l   = i >> 13;
        const float* W = l ? W2 : W1;
        const int kbase = c * 64 + kl8 * 8;
        uint4 o;
        o.x = pack_h2(W[(size_t)(kbase+0)*H_ + n], W[(size_t)(kbase+1)*H_ + n]);
        o.y = pack_h2(W[(size_t)(kbase+2)*H_ + n], W[(size_t)(kbase+3)*H_ + n]);
        o.z = pack_h2(W[(size_t)(kbase+4)*H_ + n], W[(size_t)(kbase+5)*H_ + n]);
        o.w = pack_h2(W[(size_t)(kbase+6)*H_ + n], W[(size_t)(kbase+7)*H_ + n]);
        *(uint4*)&g_Wh[(size_t)i * 4] = o;
    } else if (i < 16384 + 512) {
        const int j  = i - 16384;
        const int n  = j >> 5;
        const int k8 = (j & 31) * 8;
        uint4 o;
        o.x = pack_h2(W3[(size_t)(k8+0)*K_ + n], W3[(size_t)(k8+1)*K_ + n]);
        o.y = pack_h2(W3[(size_t)(k8+2)*K_ + n], W3[(size_t)(k8+3)*K_ + n]);
        o.z = pack_h2(W3[(size_t)(k8+4)*K_ + n], W3[(size_t)(k8+5)*K_ + n]);
        o.w = pack_h2(W3[(size_t)(k8+6)*K_ + n], W3[(size_t)(k8+7)*K_ + n]);
        *(uint4*)&g_Wh3[(size_t)j * 4] = o;
    }
}

// ---------------------------------------------------------------------------
// Kernel 1: fp16 mma.sync MLP, ldmatrix fragment loads, cp.async W chunks
// grid = 800, block = 256 (8 warps; warp grid 4(M) x 2(N))
// ---------------------------------------------------------------------------
__device__ __forceinline__ void prefetch_chunk(uint32_t sb, int tid,
                                               int layer, int cc, int buf) {
    const uint32_t* src = g_Wh + (size_t)(layer * 4 + cc) * 8192 + tid * 32;
    const uint32_t  dst = sb + (uint32_t)(BC_OFF + buf * BC_ONE + tid * CBSTW) * 4;
    #pragma unroll
    for (int j = 0; j < 8; j++) cpasync16(dst + j * 16, src + j * 4);
}
__device__ __forceinline__ void prefetch_w3(uint32_t sb, int tid) {
    #pragma unroll
    for (int q = 0; q < 2; q++) {
        const int i = tid * 2 + q;
        const int n = i >> 5, kk = i & 31;
        cpasync16(sb + (uint32_t)(W3_OFF + n * W3STW + kk * 4) * 4,
                  g_Wh3 + (size_t)i * 4);
    }
}

__global__ __launch_bounds__(256, 1)
void mlp_softk_kernel(const float* __restrict__ X,
                      const int*   __restrict__ mask,
                      const float* __restrict__ b1,
                      const float* __restrict__ b2)
{
    extern __shared__ uint32_t smu[];
    const uint32_t sb = smem_u32(smu);
    const int tid  = threadIdx.x;
    const int wid  = tid >> 5;
    const int lane = tid & 31;
    const int g    = lane >> 2;
    const int tq   = lane & 3;
    const int row0 = blockIdx.x * TM;

    prefetch_chunk(sb, tid, 0, 0, 0);
    CP_COMMIT();

    // X tile -> A (fp16)
    #pragma unroll 4
    for (int it = 0; it < 32; it++) {
        const int idx = tid + it * 256;
        const int r = idx >> 6, c4 = (idx & 63) * 4;
        const float4 v = __ldg((const float4*)(X + (size_t)(row0 + r) * H_ + c4));
        uint2 o;
        o.x = pack_h2(v.x, v.y);
        o.y = pack_h2(v.z, v.w);
        *(uint2*)&smu[r * ASTW + (c4 >> 1)] = o;
    }

    const int wm = wid & 3;        // M block: rows wm*32 .. +31
    const int wn = wid >> 2;       // N half:  cols wn*128 .. +127

    // ldmatrix per-lane address offsets (in words, before *4)
    const int q8 = lane >> 3;      // 0..3 matrix id
    const int r8 = lane & 7;       // row within matrix
    // A x4: matrices = (rows +0, k-lo), (rows +8, k-lo), (rows +0, k-hi), (rows +8, k-hi)
    int a_lane_off[2];
    #pragma unroll
    for (int mt = 0; mt < 2; mt++)
        a_lane_off[mt] = (wm * 32 + mt * 16 + (q8 & 1) * 8 + r8) * ASTW + (q8 >> 1) * 4;
    // B x4 (pair p covers n8 = 2p, 2p+1):
    // matrices = (n8a, k-lo), (n8a, k-hi), (n8b, k-lo), (n8b, k-hi)
    const int b_lane_row = (q8 >> 1) * 8 + r8;       // row within the n8-pair
    const int b_lane_kw  = (q8 & 1) * 4;

    #pragma unroll 1
    for (int layer = 0; layer < 2; layer++) {
        const float* bg = layer ? b2 : b1;

        float acc[2][16][4];
        #pragma unroll
        for (int mt = 0; mt < 2; mt++)
            #pragma unroll
            for (int n8 = 0; n8 < 16; n8++)
                #pragma unroll
                for (int i = 0; i < 4; i++) acc[mt][n8][i] = 0.0f;

        #pragma unroll 1
        for (int cc = 0; cc < 4; cc++) {
            CP_WAIT0();
            __syncthreads();     // chunk cc landed; mma reads of cc-1 done

            if (layer == 1 && cc == 3) prefetch_w3(sb, tid);
            else {
                const int nl = (cc == 3) ? 1 : layer;
                const int nc = (cc == 3) ? 0 : cc + 1;
                prefetch_chunk(sb, tid, nl, nc, (cc + 1) & 1);
            }
            CP_COMMIT();

            const uint32_t bbase = sb + (uint32_t)(BC_OFF + (cc & 1) * BC_ONE) * 4;
            #pragma unroll
            for (int ks = 0; ks < 4; ks++) {               // k-step of 16
                const int kw  = (cc * 64 + ks * 16) >> 1;  // word col in A
                const int klw = ks * 8;                    // word col in B chunk
                uint32_t a[2][4];
                #pragma unroll
                for (int mt = 0; mt < 2; mt++)
                    ldsm_x4(a[mt][0], a[mt][1], a[mt][2], a[mt][3],
                            sb + (uint32_t)(a_lane_off[mt] + kw) * 4);
                #pragma unroll
                for (int p = 0; p < 8; p++) {              // n8 pair
                    const int nrow = wn * 128 + p * 16 + b_lane_row;
                    uint32_t b0a, b1a, b0b, b1b;
                    ldsm_x4(b0a, b1a, b0b, b1b,
                            bbase + (uint32_t)(nrow * CBSTW + klw + b_lane_kw) * 4);
                    mma16(acc[0][2*p    ], a[0], b0a, b1a);
                    mma16(acc[1][2*p    ], a[1], b0a, b1a);
                    mma16(acc[0][2*p + 1], a[0], b0b, b1b);
                    mma16(acc[1][2*p + 1], a[1], b0b, b1b);
                }
            }
        }
        __syncthreads();   // all mma reads of A done -> safe to overwrite A

        // epilogue: bias + relu -> fp16 -> A
        #pragma unroll
        for (int mt = 0; mt < 2; mt++) {
            const int r = wm * 32 + mt * 16 + g;
            #pragma unroll
            for (int n8 = 0; n8 < 16; n8++) {
                const int c = wn * 128 + n8 * 8 + 2 * tq;
                const float2 bb = *(const float2*)&bg[c];
                smu[(r    ) * ASTW + (c >> 1)] =
                    pack_h2(fmaxf(acc[mt][n8][0] + bb.x, 0.f),
                            fmaxf(acc[mt][n8][1] + bb.y, 0.f));
                smu[(r + 8) * ASTW + (c >> 1)] =
                    pack_h2(fmaxf(acc[mt][n8][2] + bb.x, 0.f),
                            fmaxf(acc[mt][n8][3] + bb.y, 0.f));
            }
        }
    }

    CP_WAIT0();
    __syncthreads();     // W3 in smem; layer-2 epilogue visible

    // ---- layer 3: logits = h2 @ W3 (each warp: 16 rows) ----
    float acc3[2][4];
    #pragma unroll
    for (int n8 = 0; n8 < 2; n8++)
        #pragma unroll
        for (int i = 0; i < 4; i++) acc3[n8][i] = 0.0f;

    {
        const uint32_t* Bu3 = smu + W3_OFF;
        const int r = wid * 16 + g;
        #pragma unroll 4
        for (int ks = 0; ks < 16; ks++) {
            const int kw = ks * 8;
            uint32_t a[4];
            a[0] = smu[(r    ) * ASTW + kw + tq];
            a[1] = smu[(r + 8) * ASTW + kw + tq];
            a[2] = smu[(r    ) * ASTW + kw + tq + 4];
            a[3] = smu[(r + 8) * ASTW + kw + tq + 4];
            #pragma unroll
            for (int n8 = 0; n8 < 2; n8++) {
                const uint32_t b0 = Bu3[(n8 * 8 + g) * W3STW + kw + tq];
                const uint32_t b1v = Bu3[(n8 * 8 + g) * W3STW + kw + tq + 4];
                mma16(acc3[n8], a, b0, b1v);
            }
        }
    }

    // ---- softmax over K=16 per row, mask, /4, store ----
    #pragma unroll
    for (int p = 0; p < 2; p++) {
        const int row = row0 + wid * 16 + g + p * 8;
        float v0 = acc3[0][2 * p], v1 = acc3[0][2 * p + 1];
        float v2 = acc3[1][2 * p], v3 = acc3[1][2 * p + 1];
        float m = fmaxf(fmaxf(v0, v1), fmaxf(v2, v3));
        m = fmaxf(m, __shfl_xor_sync(0xffffffffu, m, 1));
        m = fmaxf(m, __shfl_xor_sync(0xffffffffu, m, 2));
        const float e0 = expf(v0 - m), e1 = expf(v1 - m);
        const float e2 = expf(v2 - m), e3 = expf(v3 - m);
        float ssum = e0 + e1 + e2 + e3;
        ssum += __shfl_xor_sync(0xffffffffu, ssum, 1);
        ssum += __shfl_xor_sync(0xffffffffu, ssum, 2);
        const float inv = 0.25f / ssum;             // includes /sqrt(K) = /4
        const bool mk = (mask[row] != 0);
        float2 oa, ob;
        oa.x = mk ? e0 * inv : -2500.0f;            // -10000/4
        oa.y = mk ? e1 * inv : -2500.0f;
        ob.x = mk ? e2 * inv : -2500.0f;
        ob.y = mk ? e3 * inv : -2500.0f;
        *(float2*)&g_A[(size_t)row * K_ + 2 * tq]     = oa;
        *(float2*)&g_A[(size_t)row * K_ + 8 + 2 * tq] = ob;
    }
}

// ---------------------------------------------------------------------------
// Kernel 2: softmax over S per (b,k), * time factor, out[b,k,h] = sum_s X*D
// grid = (512, 2); f32x2 FMA with explicit 8-wide load batching (MLP=8).
// ---------------------------------------------------------------------------
__device__ __forceinline__ void fma2(unsigned long long& a,
                                     unsigned long long x, unsigned long long d) {
    asm("fma.rn.f32x2 %0, %1, %2, %0;" : "+l"(a) : "l"(x), "l"(d));
}

__global__ __launch_bounds__(128, 8)
void softs_out_kernel(const float* __restrict__ X,
                      const float* __restrict__ tf,
                      float*       __restrict__ out)
{
    __shared__ __align__(16) float As[S_ * K_];   // 12.8 KB
    __shared__ float Tf[S_];
    __shared__ float Mk[K_], Ik[K_];

    const int b   = blockIdx.x;
    const int hb  = blockIdx.y;
    const int tid = threadIdx.x;

    for (int idx = tid; idx < S_ * K_; idx += 128)
        As[idx] = g_A[(size_t)b * S_ * K_ + idx];
    for (int idx = tid; idx < S_; idx += 128)
        Tf[idx] = tf[b * S_ + idx];
    __syncthreads();

    const int warp = tid >> 5, lane = tid & 31;
    for (int k = warp; k < K_; k += 4) {
        float m = -1e30f;
        for (int s = lane; s < S_; s += 32) m = fmaxf(m, As[s * K_ + k]);
        #pragma unroll
        for (int o = 16; o; o >>= 1) m = fmaxf(m, __shfl_xor_sync(0xffffffffu, m, o));
        float ssum = 0.0f;
        for (int s = lane; s < S_; s += 32) ssum += expf(As[s * K_ + k] - m);
        #pragma unroll
        for (int o = 16; o; o >>= 1) ssum += __shfl_xor_sync(0xffffffffu, ssum, o);
        if (lane == 0) { Mk[k] = m; Ik[k] = 1.0f / ssum; }
    }
    __syncthreads();

    for (int idx = tid; idx < S_ * K_; idx += 128) {
        const int s = idx >> 4, k = idx & 15;
        As[idx] = expf(As[idx] - Mk[k]) * Ik[k] * Tf[s];
    }
    __syncthreads();

    const int h = hb * 128 + tid;
    unsigned long long acc[8];
    #pragma unroll
    for (int i = 0; i < 8; i++) acc[i] = 0ull;

    const float* Xb = X + (size_t)b * S_ * H_ + h;
    #pragma unroll 1
    for (int s0 = 0; s0 < S_; s0 += 8) {       // 200 = 25 * 8
        float xv[8];
        #pragma unroll
        for (int j = 0; j < 8; j++) xv[j] = __ldg(Xb + (size_t)(s0 + j) * H_);
        #pragma unroll
        for (int j = 0; j < 8; j++) {
            unsigned long long xv2;
            asm("mov.b64 %0, {%1, %1};" : "=l"(xv2) : "f"(xv[j]));
            const unsigned long long* d =
                (const unsigned long long*)&As[(s0 + j) * K_];
            #pragma unroll
            for (int i = 0; i < 8; i++) fma2(acc[i], xv2, d[i]);
        }
    }

    float* ob = out + (size_t)b * K_ * H_ + h;
    #pragma unroll
    for (int i = 0; i < 8; i++) {
        float lo, hi;
        asm("mov.b64 {%0, %1}, %2;" : "=f"(lo), "=f"(hi) : "l"(acc[i]));
        ob[(size_t)(2 * i)     * H_] = lo;
        ob[(size_t)(2 * i + 1) * H_] = hi;
    }
}

// ---------------------------------------------------------------------------
extern "C" void kernel_launch(void* const* d_in, const int* in_sizes, int n_in,
                              void* d_out, int out_size)
{
    const float* X    = (const float*)d_in[0];   // (B,S,H)
    const int*   mask = (const int*)  d_in[1];   // (B,S,1)
    const float* tf   = (const float*)d_in[2];   // (B,S,1)
    const float* W1   = (const float*)d_in[3];
    const float* b1   = (const float*)d_in[4];
    const float* W2   = (const float*)d_in[5];
    const float* b2   = (const float*)d_in[6];
    const float* W3   = (const float*)d_in[7];
    float* out = (float*)d_out;                  // (B,K,H)

    cudaFuncSetAttribute(mlp_softk_kernel,
                         cudaFuncAttributeMaxDynamicSharedMemorySize, SM_BYTES);

    prep_kernel<<<66, 256>>>(W1, W2, W3);
    mlp_softk_kernel<<<NBLK, 256, SM_BYTES>>>(X, mask, b1, b2);
    softs_out_kernel<<<dim3(B_, 2), 128>>>(X, tf, out);
}

// round 9
// speedup vs baseline: 1.0645x; 1.0148x over previous
#include <cuda_runtime.h>
#include <cuda_fp16.h>
#include <math.h>
#include <stdint.h>

#define B_  512
#define S_  200
#define H_  256
#define K_  16
#define ROWS (B_*S_)          // 102400
#define TM  128               // rows per CTA (kernel 1)
#define NBLK (ROWS/TM)        // 800

// ---- kernel-1 smem layout (words) ----
#define ASTW  132
#define CBSTW 36
#define A_WORDS  (128*ASTW)
#define BC_OFF   A_WORDS
#define BC_ONE   (256*CBSTW)
#define W3_OFF   (BC_OFF + 2*BC_ONE)
#define W3STW 132
#define SM_WORDS (W3_OFF + 16*W3STW)
#define SM_BYTES (SM_WORDS*4)             // 149760

// ---- kernel-2 smem layout (words) ----
#define XCH   64                          // s-rows per X chunk
#define XSTW  132                         // X chunk row stride (words)
#define XBUF  (XCH*XSTW)                  // 8448
#define DS_OFF (2*XBUF)                   // 16896 ; Ds: 16 k-rows x 256 s fp16
#define DST   132
#define AF_OFF (DS_OFF + 16*DST)          // 19008 ; Af: 200x16 f32
#define TF_OFF (AF_OFF + S_*K_)
#define MK_OFF (TF_OFF + S_)
#define IK_OFF (MK_OFF + 16)
#define K2_WORDS (IK_OFF + 16)
#define K2_BYTES (K2_WORDS*4)             // 89,760 B

// scratch
__device__ float    g_A[ROWS * K_];          // masked K-softmax logits
__device__ uint32_t g_Xh[(ROWS + 56) * 128]; // X fp16 [row][h]; pad rows stay 0
__device__ uint32_t g_Wh[2 * 32768];         // W1,W2 fp16 [l][c4][n256][kl64]
__device__ uint32_t g_Wh3[16 * 128];         // W3 fp16 [n16][k256]

__device__ __forceinline__ uint32_t smem_u32(const void* p) {
    uint32_t a;
    asm("{ .reg .u64 t; cvta.to.shared.u64 t, %1; cvt.u32.u64 %0, t; }"
        : "=r"(a) : "l"(p));
    return a;
}
__device__ __forceinline__ uint32_t pack_h2(float lo, float hi) {
    const __half2 h = __floats2half2_rn(lo, hi);
    return *(const uint32_t*)&h;
}
__device__ __forceinline__ void mma16(float c[4], const uint32_t a[4],
                                      uint32_t b0, uint32_t b1) {
    asm("mma.sync.aligned.m16n8k16.row.col.f32.f16.f16.f32 "
        "{%0,%1,%2,%3}, {%4,%5,%6,%7}, {%8,%9}, {%0,%1,%2,%3};"
        : "+f"(c[0]), "+f"(c[1]), "+f"(c[2]), "+f"(c[3])
        : "r"(a[0]), "r"(a[1]), "r"(a[2]), "r"(a[3]), "r"(b0), "r"(b1));
}
__device__ __forceinline__ void ldsm_x4(uint32_t& r0, uint32_t& r1,
                                        uint32_t& r2, uint32_t& r3, uint32_t addr) {
    asm volatile("ldmatrix.sync.aligned.m8n8.x4.shared.b16 {%0,%1,%2,%3}, [%4];"
                 : "=r"(r0), "=r"(r1), "=r"(r2), "=r"(r3) : "r"(addr));
}
__device__ __forceinline__ void ldsm_x4_t(uint32_t& r0, uint32_t& r1,
                                          uint32_t& r2, uint32_t& r3, uint32_t addr) {
    asm volatile("ldmatrix.sync.aligned.m8n8.x4.trans.shared.b16 {%0,%1,%2,%3}, [%4];"
                 : "=r"(r0), "=r"(r1), "=r"(r2), "=r"(r3) : "r"(addr));
}
__device__ __forceinline__ void cpasync16(uint32_t dst, const void* src) {
    asm volatile("cp.async.cg.shared.global [%0], [%1], 16;" :: "r"(dst), "l"(src));
}
#define CP_COMMIT() asm volatile("cp.async.commit_group;" ::: "memory")
#define CP_WAIT0()  asm volatile("cp.async.wait_group 0;" ::: "memory")

// ---------------------------------------------------------------------------
// Prep: weights -> fp16 chunk-linear layouts
// ---------------------------------------------------------------------------
__global__ void prep_kernel(const float* __restrict__ W1,
                            const float* __restrict__ W2,
                            const float* __restrict__ W3)
{
    const int i = blockIdx.x * 256 + threadIdx.x;
    if (i < 16384) {
        const int kl8 = i & 7;
        const int n   = (i >> 3) & 255;
        const int c   = (i >> 11) & 3;
        const int l   = i >> 13;
        const float* W = l ? W2 : W1;
        const int kbase = c * 64 + kl8 * 8;
        uint4 o;
        o.x = pack_h2(W[(size_t)(kbase+0)*H_ + n], W[(size_t)(kbase+1)*H_ + n]);
        o.y = pack_h2(W[(size_t)(kbase+2)*H_ + n], W[(size_t)(kbase+3)*H_ + n]);
        o.z = pack_h2(W[(size_t)(kbase+4)*H_ + n], W[(size_t)(kbase+5)*H_ + n]);
        o.w = pack_h2(W[(size_t)(kbase+6)*H_ + n], W[(size_t)(kbase+7)*H_ + n]);
        *(uint4*)&g_Wh[(size_t)i * 4] = o;
    } else if (i < 16384 + 512) {
        const int j  = i - 16384;
        const int n  = j >> 5;
        const int k8 = (j & 31) * 8;
        uint4 o;
        o.x = pack_h2(W3[(size_t)(k8+0)*K_ + n], W3[(size_t)(k8+1)*K_ + n]);
        o.y = pack_h2(W3[(size_t)(k8+2)*K_ + n], W3[(size_t)(k8+3)*K_ + n]);
        o.z = pack_h2(W3[(size_t)(k8+4)*K_ + n], W3[(size_t)(k8+5)*K_ + n]);
        o.w = pack_h2(W3[(size_t)(k8+6)*K_ + n], W3[(size_t)(k8+7)*K_ + n]);
        *(uint4*)&g_Wh3[(size_t)j * 4] = o;
    }
}

// ---------------------------------------------------------------------------
// Kernel 1: fp16 mma.sync MLP (round-8 version) + X fp16 export to g_Xh
// ---------------------------------------------------------------------------
__device__ __forceinline__ void prefetch_chunk(uint32_t sb, int tid,
                                               int layer, int cc, int buf) {
    const uint32_t* src = g_Wh + (size_t)(layer * 4 + cc) * 8192 + tid * 32;
    const uint32_t  dst = sb + (uint32_t)(BC_OFF + buf * BC_ONE + tid * CBSTW) * 4;
    #pragma unroll
    for (int j = 0; j < 8; j++) cpasync16(dst + j * 16, src + j * 4);
}
__device__ __forceinline__ void prefetch_w3(uint32_t sb, int tid) {
    #pragma unroll
    for (int q = 0; q < 2; q++) {
        const int i = tid * 2 + q;
        const int n = i >> 5, kk = i & 31;
        cpasync16(sb + (uint32_t)(W3_OFF + n * W3STW + kk * 4) * 4,
                  g_Wh3 + (size_t)i * 4);
    }
}

__global__ __launch_bounds__(256, 1)
void mlp_softk_kernel(const float* __restrict__ X,
                      const int*   __restrict__ mask,
                      const float* __restrict__ b1,
                      const float* __restrict__ b2)
{
    extern __shared__ uint32_t smu[];
    const uint32_t sb = smem_u32(smu);
    const int tid  = threadIdx.x;
    const int wid  = tid >> 5;
    const int lane = tid & 31;
    const int g    = lane >> 2;
    const int tq   = lane & 3;
    const int row0 = blockIdx.x * TM;

    prefetch_chunk(sb, tid, 0, 0, 0);
    CP_COMMIT();

    // X tile -> A (fp16) + export fp16 X to g_Xh
    #pragma unroll 4
    for (int it = 0; it < 32; it++) {
        const int idx = tid + it * 256;
        const int r = idx >> 6, c4 = (idx & 63) * 4;
        const float4 v = __ldg((const float4*)(X + (size_t)(row0 + r) * H_ + c4));
        uint2 o;
        o.x = pack_h2(v.x, v.y);
        o.y = pack_h2(v.z, v.w);
        *(uint2*)&smu[r * ASTW + (c4 >> 1)] = o;
        *(uint2*)&g_Xh[(size_t)(row0 + r) * 128 + (c4 >> 1)] = o;
    }

    const int wm = wid & 3;        // M block: rows wm*32 .. +31
    const int wn = wid >> 2;       // N half:  cols wn*128 .. +127

    const int q8 = lane >> 3;
    const int r8 = lane & 7;
    int a_lane_off[2];
    #pragma unroll
    for (int mt = 0; mt < 2; mt++)
        a_lane_off[mt] = (wm * 32 + mt * 16 + (q8 & 1) * 8 + r8) * ASTW + (q8 >> 1) * 4;
    const int b_lane_row = (q8 >> 1) * 8 + r8;
    const int b_lane_kw  = (q8 & 1) * 4;

    #pragma unroll 1
    for (int layer = 0; layer < 2; layer++) {
        const float* bg = layer ? b2 : b1;

        float acc[2][16][4];
        #pragma unroll
        for (int mt = 0; mt < 2; mt++)
            #pragma unroll
            for (int n8 = 0; n8 < 16; n8++)
                #pragma unroll
                for (int i = 0; i < 4; i++) acc[mt][n8][i] = 0.0f;

        #pragma unroll 1
        for (int cc = 0; cc < 4; cc++) {
            CP_WAIT0();
            __syncthreads();

            if (layer == 1 && cc == 3) prefetch_w3(sb, tid);
            else {
                const int nl = (cc == 3) ? 1 : layer;
                const int nc = (cc == 3) ? 0 : cc + 1;
                prefetch_chunk(sb, tid, nl, nc, (cc + 1) & 1);
            }
            CP_COMMIT();

            const uint32_t bbase = sb + (uint32_t)(BC_OFF + (cc & 1) * BC_ONE) * 4;
            #pragma unroll
            for (int ks = 0; ks < 4; ks++) {
                const int kw  = (cc * 64 + ks * 16) >> 1;
                const int klw = ks * 8;
                uint32_t a[2][4];
                #pragma unroll
                for (int mt = 0; mt < 2; mt++)
                    ldsm_x4(a[mt][0], a[mt][1], a[mt][2], a[mt][3],
                            sb + (uint32_t)(a_lane_off[mt] + kw) * 4);
                #pragma unroll
                for (int p = 0; p < 8; p++) {
                    const int nrow = wn * 128 + p * 16 + b_lane_row;
                    uint32_t b0a, b1a, b0b, b1b;
                    ldsm_x4(b0a, b1a, b0b, b1b,
                            bbase + (uint32_t)(nrow * CBSTW + klw + b_lane_kw) * 4);
                    mma16(acc[0][2*p    ], a[0], b0a, b1a);
                    mma16(acc[1][2*p    ], a[1], b0a, b1a);
                    mma16(acc[0][2*p + 1], a[0], b0b, b1b);
                    mma16(acc[1][2*p + 1], a[1], b0b, b1b);
                }
            }
        }
        __syncthreads();

        // epilogue: bias + relu -> fp16 -> A
        #pragma unroll
        for (int mt = 0; mt < 2; mt++) {
            const int r = wm * 32 + mt * 16 + g;
            #pragma unroll
            for (int n8 = 0; n8 < 16; n8++) {
                const int c = wn * 128 + n8 * 8 + 2 * tq;
                const float2 bb = *(const float2*)&bg[c];
                smu[(r    ) * ASTW + (c >> 1)] =
                    pack_h2(fmaxf(acc[mt][n8][0] + bb.x, 0.f),
                            fmaxf(acc[mt][n8][1] + bb.y, 0.f));
                smu[(r + 8) * ASTW + (c >> 1)] =
                    pack_h2(fmaxf(acc[mt][n8][2] + bb.x, 0.f),
                            fmaxf(acc[mt][n8][3] + bb.y, 0.f));
            }
        }
    }

    CP_WAIT0();
    __syncthreads();

    // ---- layer 3: logits = h2 @ W3 ----
    float acc3[2][4];
    #pragma unroll
    for (int n8 = 0; n8 < 2; n8++)
        #pragma unroll
        for (int i = 0; i < 4; i++) acc3[n8][i] = 0.0f;

    {
        const uint32_t* Bu3 = smu + W3_OFF;
        const int r = wid * 16 + g;
        #pragma unroll 4
        for (int ks = 0; ks < 16; ks++) {
            const int kw = ks * 8;
            uint32_t a[4];
            a[0] = smu[(r    ) * ASTW + kw + tq];
            a[1] = smu[(r + 8) * ASTW + kw + tq];
            a[2] = smu[(r    ) * ASTW + kw + tq + 4];
            a[3] = smu[(r + 8) * ASTW + kw + tq + 4];
            #pragma unroll
            for (int n8 = 0; n8 < 2; n8++) {
                const uint32_t b0 = Bu3[(n8 * 8 + g) * W3STW + kw + tq];
                const uint32_t b1v = Bu3[(n8 * 8 + g) * W3STW + kw + tq + 4];
                mma16(acc3[n8], a, b0, b1v);
            }
        }
    }

    // ---- softmax over K=16 per row, mask, /4, store ----
    #pragma unroll
    for (int p = 0; p < 2; p++) {
        const int row = row0 + wid * 16 + g + p * 8;
        float v0 = acc3[0][2 * p], v1 = acc3[0][2 * p + 1];
        float v2 = acc3[1][2 * p], v3 = acc3[1][2 * p + 1];
        float m = fmaxf(fmaxf(v0, v1), fmaxf(v2, v3));
        m = fmaxf(m, __shfl_xor_sync(0xffffffffu, m, 1));
        m = fmaxf(m, __shfl_xor_sync(0xffffffffu, m, 2));
        const float e0 = expf(v0 - m), e1 = expf(v1 - m);
        const float e2 = expf(v2 - m), e3 = expf(v3 - m);
        float ssum = e0 + e1 + e2 + e3;
        ssum += __shfl_xor_sync(0xffffffffu, ssum, 1);
        ssum += __shfl_xor_sync(0xffffffffu, ssum, 2);
        const float inv = 0.25f / ssum;
        const bool mk = (mask[row] != 0);
        float2 oa, ob;
        oa.x = mk ? e0 * inv : -2500.0f;
        oa.y = mk ? e1 * inv : -2500.0f;
        ob.x = mk ? e2 * inv : -2500.0f;
        ob.y = mk ? e3 * inv : -2500.0f;
        *(float2*)&g_A[(size_t)row * K_ + 2 * tq]     = oa;
        *(float2*)&g_A[(size_t)row * K_ + 8 + 2 * tq] = ob;
    }
}

// ---------------------------------------------------------------------------
// Kernel 2: per batch — S-softmax + time factor -> D^T fp16, then
// out[b](16x256) = D^T(16x256,s-pad) @ X_fp16(256x256) via mma + ldmatrix.
// grid = 512, block = 256 (8 warps; warp w owns h = w*32 .. +31)
// ---------------------------------------------------------------------------
__global__ __launch_bounds__(256, 2)
void out_gemm_kernel(const float* __restrict__ tf,
                     float*       __restrict__ out)
{
    extern __shared__ uint32_t smu[];
    const uint32_t sb = smem_u32(smu);
    const int tid  = threadIdx.x;
    const int wid  = tid >> 5;
    const int lane = tid & 31;
    const int g    = lane >> 2;
    const int tq   = lane & 3;
    const int b    = blockIdx.x;

    // prefetch X chunk 0 (64 rows x 512B)
    {
        const uint32_t* src = g_Xh + (size_t)(b * S_) * 128;
        #pragma unroll
        for (int j = 0; j < 8; j++) {
            const int line = tid + j * 256;
            const int r = line >> 5, lw = line & 31;
            cpasync16(sb + (uint32_t)(r * XSTW + lw * 4) * 4, src + r * 128 + lw * 4);
        }
        CP_COMMIT();
    }

    float* Af = (float*)(smu + AF_OFF);
    float* Tf = (float*)(smu + TF_OFF);
    float* Mk = (float*)(smu + MK_OFF);
    float* Ik = (float*)(smu + IK_OFF);

    for (int idx = tid; idx < S_ * K_; idx += 256)
        Af[idx] = g_A[(size_t)b * S_ * K_ + idx];
    for (int idx = tid; idx < S_; idx += 256)
        Tf[idx] = tf[b * S_ + idx];
    __syncthreads();

    // per-k softmax stats: warp w -> k = w, w+8
    #pragma unroll
    for (int kk = 0; kk < 2; kk++) {
        const int k = wid + kk * 8;
        float m = -1e30f;
        for (int s = lane; s < S_; s += 32) m = fmaxf(m, Af[s * K_ + k]);
        #pragma unroll
        for (int o = 16; o; o >>= 1) m = fmaxf(m, __shfl_xor_sync(0xffffffffu, m, o));
        float ss = 0.0f;
        for (int s = lane; s < S_; s += 32) ss += expf(Af[s * K_ + k] - m);
        #pragma unroll
        for (int o = 16; o; o >>= 1) ss += __shfl_xor_sync(0xffffffffu, ss, o);
        if (lane == 0) { Mk[k] = m; Ik[k] = 1.0f / ss; }
    }
    __syncthreads();

    // write Ds[k][s] fp16 (s padded to 256 with zeros)
    for (int idx = tid; idx < 16 * 128; idx += 256) {
        const int k = idx >> 7, sw = idx & 127, s0 = sw * 2;
        float v0 = 0.0f, v1 = 0.0f;
        if (s0     < S_) v0 = expf(Af[s0 * K_ + k]       - Mk[k]) * Ik[k] * Tf[s0];
        if (s0 + 1 < S_) v1 = expf(Af[(s0 + 1) * K_ + k] - Mk[k]) * Ik[k] * Tf[s0 + 1];
        smu[DS_OFF + k * DST + sw] = pack_h2(v0, v1);
    }

    float acc[4][4];
    #pragma unroll
    for (int n8 = 0; n8 < 4; n8++)
        #pragma unroll
        for (int i = 0; i < 4; i++) acc[n8][i] = 0.0f;

    const int q8 = lane >> 3, r8 = lane & 7;
    const int a_off  = DS_OFF + ((q8 & 1) * 8 + r8) * DST + (q8 >> 1) * 4;
    const int b_srow = (q8 & 1) * 8 + r8;          // s row within 16-tile
    const int b_hw   = wid * 16 + (q8 >> 1) * 4;   // h word offset (per pair +8)

    #pragma unroll 1
    for (int c = 0; c < 4; c++) {
        CP_WAIT0();
        __syncthreads();    // chunk c + Ds visible; prior buffer reads done
        if (c < 3) {
            const uint32_t* src = g_Xh + (size_t)(b * S_ + (c + 1) * XCH) * 128;
            const uint32_t dbuf = sb + (uint32_t)(((c + 1) & 1) * XBUF) * 4;
            #pragma unroll
            for (int j = 0; j < 8; j++) {
                const int line = tid + j * 256;
                const int r = line >> 5, lw = line & 31;
                cpasync16(dbuf + (uint32_t)(r * XSTW + lw * 4) * 4,
                          src + r * 128 + lw * 4);
            }
            CP_COMMIT();
        }
        const uint32_t xbuf = sb + (uint32_t)((c & 1) * XBUF) * 4;
        #pragma unroll
        for (int ks = 0; ks < 4; ks++) {
            uint32_t a[4];
            ldsm_x4(a[0], a[1], a[2], a[3],
                    sb + (uint32_t)(a_off + c * 32 + ks * 8) * 4);
            #pragma unroll
            for (int p = 0; p < 2; p++) {
                uint32_t r0, r1, r2, r3;
                ldsm_x4_t(r0, r1, r2, r3,
                    xbuf + (uint32_t)((ks * 16 + b_srow) * XSTW + b_hw + p * 8) * 4);
                mma16(acc[2 * p    ], a, r0, r1);
                mma16(acc[2 * p + 1], a, r2, r3);
            }
        }
    }

    // store out[b][k][h]
    float* ob = out + (size_t)b * K_ * H_;
    #pragma unroll
    for (int n8 = 0; n8 < 4; n8++) {
        const int h = wid * 32 + n8 * 8 + 2 * tq;
        *(float2*)&ob[(g    ) * H_ + h] = make_float2(acc[n8][0], acc[n8][1]);
        *(float2*)&ob[(g + 8) * H_ + h] = make_float2(acc[n8][2], acc[n8][3]);
    }
}

// ---------------------------------------------------------------------------
extern "C" void kernel_launch(void* const* d_in, const int* in_sizes, int n_in,
                              void* d_out, int out_size)
{
    const float* X    = (const float*)d_in[0];   // (B,S,H)
    const int*   mask = (const int*)  d_in[1];   // (B,S,1)
    const float* tf   = (const float*)d_in[2];   // (B,S,1)
    const float* W1   = (const float*)d_in[3];
    const float* b1   = (const float*)d_in[4];
    const float* W2   = (const float*)d_in[5];
    const float* b2   = (const float*)d_in[6];
    const float* W3   = (const float*)d_in[7];
    float* out = (float*)d_out;                  // (B,K,H)

    cudaFuncSetAttribute(mlp_softk_kernel,
                         cudaFuncAttributeMaxDynamicSharedMemorySize, SM_BYTES);
    cudaFuncSetAttribute(out_gemm_kernel,
                         cudaFuncAttributeMaxDynamicSharedMemorySize, K2_BYTES);

    prep_kernel<<<66, 256>>>(W1, W2, W3);
    mlp_softk_kernel<<<NBLK, 256, SM_BYTES>>>(X, mask, b1, b2);
    out_gemm_kernel<<<B_, 256, K2_BYTES>>>(tf, out);
}

// round 10
// speedup vs baseline: 1.0737x; 1.0087x over previous
#include <cuda_runtime.h>
#include <cuda_fp16.h>
#include <math.h>
#include <stdint.h>

#define B_  512
#define S_  200
#define H_  256
#define K_  16
#define ROWS (B_*S_)          // 102400
#define TM  128               // rows per CTA (kernel 1)
#define NBLK (ROWS/TM)        // 800

// ---- kernel-1 smem layout (words) ----
#define ASTW  132
#define CBSTW 36
#define A_WORDS  (128*ASTW)
#define BC_OFF   A_WORDS
#define BC_ONE   (256*CBSTW)
#define W3_OFF   (BC_OFF + 2*BC_ONE)
#define W3STW 132
#define SM_WORDS (W3_OFF + 16*W3STW)
#define SM_BYTES (SM_WORDS*4)             // 149760

// ---- kernel-2 smem layout (words): per-CTA = one h-half of one batch ----
#define XCH    64                         // s-rows per X chunk
#define XSTW2  68                         // X chunk row stride (words, 16B-mult)
#define XBUF2  (XCH*XSTW2)                // 4352
#define DS2_OFF (2*XBUF2)                 // 8704 ; Ds: 16 k-rows x 256 s fp16
#define DST2   132
#define AFST   17                         // Af row stride (words) - conflict-free
#define AF2_OFF (DS2_OFF + 16*DST2)       // 10816
#define TF2_OFF (AF2_OFF + S_*AFST)       // 14216
#define MK2_OFF (TF2_OFF + S_)            // 14416
#define IK2_OFF (MK2_OFF + 16)
#define K2_WORDS (IK2_OFF + 16)           // 14448
#define K2_BYTES (K2_WORDS*4)             // 57792

// scratch
__device__ float    g_A[ROWS * K_];          // masked K-softmax logits
__device__ uint32_t g_Xh[(ROWS + 56) * 128]; // X fp16 [row][h]; pad rows stay 0
__device__ uint32_t g_Wh[2 * 32768];         // W1,W2 fp16 [l][c4][n256][kl64]
__device__ uint32_t g_Wh3[16 * 128];         // W3 fp16 [n16][k256]

__device__ __forceinline__ uint32_t smem_u32(const void* p) {
    uint32_t a;
    asm("{ .reg .u64 t; cvta.to.shared.u64 t, %1; cvt.u32.u64 %0, t; }"
        : "=r"(a) : "l"(p));
    return a;
}
__device__ __forceinline__ uint32_t pack_h2(float lo, float hi) {
    const __half2 h = __floats2half2_rn(lo, hi);
    return *(const uint32_t*)&h;
}
__device__ __forceinline__ void mma16(float c[4], const uint32_t a[4],
                                      uint32_t b0, uint32_t b1) {
    asm("mma.sync.aligned.m16n8k16.row.col.f32.f16.f16.f32 "
        "{%0,%1,%2,%3}, {%4,%5,%6,%7}, {%8,%9}, {%0,%1,%2,%3};"
        : "+f"(c[0]), "+f"(c[1]), "+f"(c[2]), "+f"(c[3])
        : "r"(a[0]), "r"(a[1]), "r"(a[2]), "r"(a[3]), "r"(b0), "r"(b1));
}
__device__ __forceinline__ void ldsm_x4(uint32_t& r0, uint32_t& r1,
                                        uint32_t& r2, uint32_t& r3, uint32_t addr) {
    asm volatile("ldmatrix.sync.aligned.m8n8.x4.shared.b16 {%0,%1,%2,%3}, [%4];"
                 : "=r"(r0), "=r"(r1), "=r"(r2), "=r"(r3) : "r"(addr));
}
__device__ __forceinline__ void ldsm_x4_t(uint32_t& r0, uint32_t& r1,
                                          uint32_t& r2, uint32_t& r3, uint32_t addr) {
    asm volatile("ldmatrix.sync.aligned.m8n8.x4.trans.shared.b16 {%0,%1,%2,%3}, [%4];"
                 : "=r"(r0), "=r"(r1), "=r"(r2), "=r"(r3) : "r"(addr));
}
__device__ __forceinline__ void cpasync16(uint32_t dst, const void* src) {
    asm volatile("cp.async.cg.shared.global [%0], [%1], 16;" :: "r"(dst), "l"(src));
}
#define CP_COMMIT() asm volatile("cp.async.commit_group;" ::: "memory")
#define CP_WAIT0()  asm volatile("cp.async.wait_group 0;" ::: "memory")

// ---------------------------------------------------------------------------
// Prep: weights -> fp16 chunk-linear layouts (unchanged, passing)
// ---------------------------------------------------------------------------
__global__ void prep_kernel(const float* __restrict__ W1,
                            const float* __restrict__ W2,
                            const float* __restrict__ W3)
{
    const int i = blockIdx.x * 256 + threadIdx.x;
    if (i < 16384) {
        const int kl8 = i & 7;
        const int n   = (i >> 3) & 255;
        const int c   = (i >> 11) & 3;
        const int l   = i >> 13;
        const float* W = l ? W2 : W1;
        const int kbase = c * 64 + kl8 * 8;
        uint4 o;
        o.x = pack_h2(W[(size_t)(kbase+0)*H_ + n], W[(size_t)(kbase+1)*H_ + n]);
        o.y = pack_h2(W[(size_t)(kbase+2)*H_ + n], W[(size_t)(kbase+3)*H_ + n]);
        o.z = pack_h2(W[(size_t)(kbase+4)*H_ + n], W[(size_t)(kbase+5)*H_ + n]);
        o.w = pack_h2(W[(size_t)(kbase+6)*H_ + n], W[(size_t)(kbase+7)*H_ + n]);
        *(uint4*)&g_Wh[(size_t)i * 4] = o;
    } else if (i < 16384 + 512) {
        const int j  = i - 16384;
        const int n  = j >> 5;
        const int k8 = (j & 31) * 8;
        uint4 o;
        o.x = pack_h2(W3[(size_t)(k8+0)*K_ + n], W3[(size_t)(k8+1)*K_ + n]);
        o.y = pack_h2(W3[(size_t)(k8+2)*K_ + n], W3[(size_t)(k8+3)*K_ + n]);
        o.z = pack_h2(W3[(size_t)(k8+4)*K_ + n], W3[(size_t)(k8+5)*K_ + n]);
        o.w = pack_h2(W3[(size_t)(k8+6)*K_ + n], W3[(size_t)(k8+7)*K_ + n]);
        *(uint4*)&g_Wh3[(size_t)j * 4] = o;
    }
}

// ---------------------------------------------------------------------------
// Kernel 1: fp16 mma.sync MLP + X fp16 export (unchanged, passing @ round 9)
// ---------------------------------------------------------------------------
__device__ __forceinline__ void prefetch_chunk(uint32_t sb, int tid,
                                               int layer, int cc, int buf) {
    const uint32_t* src = g_Wh + (size_t)(layer * 4 + cc) * 8192 + tid * 32;
    const uint32_t  dst = sb + (uint32_t)(BC_OFF + buf * BC_ONE + tid * CBSTW) * 4;
    #pragma unroll
    for (int j = 0; j < 8; j++) cpasync16(dst + j * 16, src + j * 4);
}
__device__ __forceinline__ void prefetch_w3(uint32_t sb, int tid) {
    #pragma unroll
    for (int q = 0; q < 2; q++) {
        const int i = tid * 2 + q;
        const int n = i >> 5, kk = i & 31;
        cpasync16(sb + (uint32_t)(W3_OFF + n * W3STW + kk * 4) * 4,
                  g_Wh3 + (size_t)i * 4);
    }
}

__global__ __launch_bounds__(256, 1)
void mlp_softk_kernel(const float* __restrict__ X,
                      const int*   __restrict__ mask,
                      const float* __restrict__ b1,
                      const float* __restrict__ b2)
{
    extern __shared__ uint32_t smu[];
    const uint32_t sb = smem_u32(smu);
    const int tid  = threadIdx.x;
    const int wid  = tid >> 5;
    const int lane = tid & 31;
    const int g    = lane >> 2;
    const int tq   = lane & 3;
    const int row0 = blockIdx.x * TM;

    prefetch_chunk(sb, tid, 0, 0, 0);
    CP_COMMIT();

    #pragma unroll 4
    for (int it = 0; it < 32; it++) {
        const int idx = tid + it * 256;
        const int r = idx >> 6, c4 = (idx & 63) * 4;
        const float4 v = __ldg((const float4*)(X + (size_t)(row0 + r) * H_ + c4));
        uint2 o;
        o.x = pack_h2(v.x, v.y);
        o.y = pack_h2(v.z, v.w);
        *(uint2*)&smu[r * ASTW + (c4 >> 1)] = o;
        *(uint2*)&g_Xh[(size_t)(row0 + r) * 128 + (c4 >> 1)] = o;
    }

    const int wm = wid & 3;
    const int wn = wid >> 2;

    const int q8 = lane >> 3;
    const int r8 = lane & 7;
    int a_lane_off[2];
    #pragma unroll
    for (int mt = 0; mt < 2; mt++)
        a_lane_off[mt] = (wm * 32 + mt * 16 + (q8 & 1) * 8 + r8) * ASTW + (q8 >> 1) * 4;
    const int b_lane_row = (q8 >> 1) * 8 + r8;
    const int b_lane_kw  = (q8 & 1) * 4;

    #pragma unroll 1
    for (int layer = 0; layer < 2; layer++) {
        const float* bg = layer ? b2 : b1;

        float acc[2][16][4];
        #pragma unroll
        for (int mt = 0; mt < 2; mt++)
            #pragma unroll
            for (int n8 = 0; n8 < 16; n8++)
                #pragma unroll
                for (int i = 0; i < 4; i++) acc[mt][n8][i] = 0.0f;

        #pragma unroll 1
        for (int cc = 0; cc < 4; cc++) {
            CP_WAIT0();
            __syncthreads();

            if (layer == 1 && cc == 3) prefetch_w3(sb, tid);
            else {
                const int nl = (cc == 3) ? 1 : layer;
                const int nc = (cc == 3) ? 0 : cc + 1;
                prefetch_chunk(sb, tid, nl, nc, (cc + 1) & 1);
            }
            CP_COMMIT();

            const uint32_t bbase = sb + (uint32_t)(BC_OFF + (cc & 1) * BC_ONE) * 4;
            #pragma unroll
            for (int ks = 0; ks < 4; ks++) {
                const int kw  = (cc * 64 + ks * 16) >> 1;
                const int klw = ks * 8;
                uint32_t a[2][4];
                #pragma unroll
                for (int mt = 0; mt < 2; mt++)
                    ldsm_x4(a[mt][0], a[mt][1], a[mt][2], a[mt][3],
                            sb + (uint32_t)(a_lane_off[mt] + kw) * 4);
                #pragma unroll
                for (int p = 0; p < 8; p++) {
                    const int nrow = wn * 128 + p * 16 + b_lane_row;
                    uint32_t b0a, b1a, b0b, b1b;
                    ldsm_x4(b0a, b1a, b0b, b1b,
                            bbase + (uint32_t)(nrow * CBSTW + klw + b_lane_kw) * 4);
                    mma16(acc[0][2*p    ], a[0], b0a, b1a);
                    mma16(acc[1][2*p    ], a[1], b0a, b1a);
                    mma16(acc[0][2*p + 1], a[0], b0b, b1b);
                    mma16(acc[1][2*p + 1], a[1], b0b, b1b);
                }
            }
        }
        __syncthreads();

        #pragma unroll
        for (int mt = 0; mt < 2; mt++) {
            const int r = wm * 32 + mt * 16 + g;
            #pragma unroll
            for (int n8 = 0; n8 < 16; n8++) {
                const int c = wn * 128 + n8 * 8 + 2 * tq;
                const float2 bb = *(const float2*)&bg[c];
                smu[(r    ) * ASTW + (c >> 1)] =
                    pack_h2(fmaxf(acc[mt][n8][0] + bb.x, 0.f),
                            fmaxf(acc[mt][n8][1] + bb.y, 0.f));
                smu[(r + 8) * ASTW + (c >> 1)] =
                    pack_h2(fmaxf(acc[mt][n8][2] + bb.x, 0.f),
                            fmaxf(acc[mt][n8][3] + bb.y, 0.f));
            }
        }
    }

    CP_WAIT0();
    __syncthreads();

    float acc3[2][4];
    #pragma unroll
    for (int n8 = 0; n8 < 2; n8++)
        #pragma unroll
        for (int i = 0; i < 4; i++) acc3[n8][i] = 0.0f;

    {
        const uint32_t* Bu3 = smu + W3_OFF;
        const int r = wid * 16 + g;
        #pragma unroll 4
        for (int ks = 0; ks < 16; ks++) {
            const int kw = ks * 8;
            uint32_t a[4];
            a[0] = smu[(r    ) * ASTW + kw + tq];
            a[1] = smu[(r + 8) * ASTW + kw + tq];
            a[2] = smu[(r    ) * ASTW + kw + tq + 4];
            a[3] = smu[(r + 8) * ASTW + kw + tq + 4];
            #pragma unroll
            for (int n8 = 0; n8 < 2; n8++) {
                const uint32_t b0 = Bu3[(n8 * 8 + g) * W3STW + kw + tq];
                const uint32_t b1v = Bu3[(n8 * 8 + g) * W3STW + kw + tq + 4];
                mma16(acc3[n8], a, b0, b1v);
            }
        }
    }

    #pragma unroll
    for (int p = 0; p < 2; p++) {
        const int row = row0 + wid * 16 + g + p * 8;
        float v0 = acc3[0][2 * p], v1 = acc3[0][2 * p + 1];
        float v2 = acc3[1][2 * p], v3 = acc3[1][2 * p + 1];
        float m = fmaxf(fmaxf(v0, v1), fmaxf(v2, v3));
        m = fmaxf(m, __shfl_xor_sync(0xffffffffu, m, 1));
        m = fmaxf(m, __shfl_xor_sync(0xffffffffu, m, 2));
        const float e0 = expf(v0 - m), e1 = expf(v1 - m);
        const float e2 = expf(v2 - m), e3 = expf(v3 - m);
        float ssum = e0 + e1 + e2 + e3;
        ssum += __shfl_xor_sync(0xffffffffu, ssum, 1);
        ssum += __shfl_xor_sync(0xffffffffu, ssum, 2);
        const float inv = 0.25f / ssum;
        const bool mk = (mask[row] != 0);
        float2 oa, ob;
        oa.x = mk ? e0 * inv : -2500.0f;
        oa.y = mk ? e1 * inv : -2500.0f;
        ob.x = mk ? e2 * inv : -2500.0f;
        ob.y = mk ? e3 * inv : -2500.0f;
        *(float2*)&g_A[(size_t)row * K_ + 2 * tq]     = oa;
        *(float2*)&g_A[(size_t)row * K_ + 8 + 2 * tq] = ob;
    }
}

// ---------------------------------------------------------------------------
// Kernel 2: grid (512, 2) — CTA = (batch, h-half). 128 threads, 4 warps.
// S-softmax + time factor -> D^T fp16, then 16x128x256 slice of the output
// GEMM on the tensor pipe. Smaller CTA -> 3+/SM resident, short serial chain.
// ---------------------------------------------------------------------------
__global__ __launch_bounds__(128, 4)
void out_gemm_kernel(const float* __restrict__ tf,
                     float*       __restrict__ out)
{
    extern __shared__ uint32_t smu[];
    const uint32_t sb = smem_u32(smu);
    const int tid  = threadIdx.x;
    const int w    = tid >> 5;          // 0..3
    const int lane = tid & 31;
    const int g    = lane >> 2;
    const int tq   = lane & 3;
    const int b    = blockIdx.x;
    const int hb   = blockIdx.y;        // h-half: cols hb*128 .. +127

    // prefetch X chunk 0: 64 rows x 128 h fp16 = 16KB (1024 16B lines)
    {
        const uint32_t* src = g_Xh + (size_t)(b * S_) * 128 + hb * 64;
        #pragma unroll
        for (int j = 0; j < 8; j++) {
            const int line = tid + j * 128;
            const int r = line >> 4, lw = line & 15;
            cpasync16(sb + (uint32_t)(r * XSTW2 + lw * 4) * 4,
                      src + (size_t)r * 128 + lw * 4);
        }
        CP_COMMIT();
    }

    float* Af = (float*)(smu + AF2_OFF);
    float* Tf = (float*)(smu + TF2_OFF);
    float* Mk = (float*)(smu + MK2_OFF);
    float* Ik = (float*)(smu + IK2_OFF);

    for (int idx = tid; idx < S_ * K_; idx += 128) {
        const int s = idx >> 4, k = idx & 15;
        Af[s * AFST + k] = g_A[(size_t)b * S_ * K_ + idx];
    }
    for (int idx = tid; idx < S_; idx += 128)
        Tf[idx] = tf[b * S_ + idx];
    __syncthreads();

    // per-k softmax stats: warp w -> k = w, w+4, w+8, w+12 (conflict-free LDS)
    #pragma unroll
    for (int kk = 0; kk < 4; kk++) {
        const int k = w + kk * 4;
        float m = -1e30f;
        for (int s = lane; s < S_; s += 32) m = fmaxf(m, Af[s * AFST + k]);
        #pragma unroll
        for (int o = 16; o; o >>= 1) m = fmaxf(m, __shfl_xor_sync(0xffffffffu, m, o));
        float ss = 0.0f;
        for (int s = lane; s < S_; s += 32) ss += expf(Af[s * AFST + k] - m);
        #pragma unroll
        for (int o = 16; o; o >>= 1) ss += __shfl_xor_sync(0xffffffffu, ss, o);
        if (lane == 0) { Mk[k] = m; Ik[k] = 1.0f / ss; }
    }
    __syncthreads();

    // Ds[k][s] fp16 (s padded to 256 with zeros)
    for (int idx = tid; idx < 16 * 128; idx += 128) {
        const int k = idx >> 7, sw = idx & 127, s0 = sw * 2;
        float v0 = 0.0f, v1 = 0.0f;
        if (s0     < S_) v0 = expf(Af[s0 * AFST + k]       - Mk[k]) * Ik[k] * Tf[s0];
        if (s0 + 1 < S_) v1 = expf(Af[(s0 + 1) * AFST + k] - Mk[k]) * Ik[k] * Tf[s0 + 1];
        smu[DS2_OFF + k * DST2 + sw] = pack_h2(v0, v1);
    }

    float acc[4][4];
    #pragma unroll
    for (int n8 = 0; n8 < 4; n8++)
        #pragma unroll
        for (int i = 0; i < 4; i++) acc[n8][i] = 0.0f;

    const int q8 = lane >> 3, r8 = lane & 7;
    const int a_off  = DS2_OFF + ((q8 & 1) * 8 + r8) * DST2 + (q8 >> 1) * 4;
    const int b_srow = (q8 & 1) * 8 + r8;          // s row within 16-tile
    const int b_hw   = w * 16 + (q8 >> 1) * 4;     // h word offset (local)

    #pragma unroll 1
    for (int c = 0; c < 4; c++) {
        CP_WAIT0();
        __syncthreads();    // chunk c + Ds visible; prior buffer reads done
        if (c < 3) {
            const uint32_t* src = g_Xh + (size_t)(b * S_ + (c + 1) * XCH) * 128 + hb * 64;
            const uint32_t dbuf = sb + (uint32_t)(((c + 1) & 1) * XBUF2) * 4;
            #pragma unroll
            for (int j = 0; j < 8; j++) {
                const int line = tid + j * 128;
                const int r = line >> 4, lw = line & 15;
                cpasync16(dbuf + (uint32_t)(r * XSTW2 + lw * 4) * 4,
                          src + (size_t)r * 128 + lw * 4);
            }
            CP_COMMIT();
        }
        const uint32_t xbuf = sb + (uint32_t)((c & 1) * XBUF2) * 4;
        #pragma unroll
        for (int ks = 0; ks < 4; ks++) {
            uint32_t a[4];
            ldsm_x4(a[0], a[1], a[2], a[3],
                    sb + (uint32_t)(a_off + c * 32 + ks * 8) * 4);
            #pragma unroll
            for (int p = 0; p < 2; p++) {
                uint32_t r0, r1, r2, r3;
                ldsm_x4_t(r0, r1, r2, r3,
                    xbuf + (uint32_t)((ks * 16 + b_srow) * XSTW2 + b_hw + p * 8) * 4);
                mma16(acc[2 * p    ], a, r0, r1);
                mma16(acc[2 * p + 1], a, r2, r3);
            }
        }
    }

    // store out[b][k][h]
    float* ob = out + (size_t)b * K_ * H_ + hb * 128;
    #pragma unroll
    for (int n8 = 0; n8 < 4; n8++) {
        const int h = w * 32 + n8 * 8 + 2 * tq;
        *(float2*)&ob[(g    ) * H_ + h] = make_float2(acc[n8][0], acc[n8][1]);
        *(float2*)&ob[(g + 8) * H_ + h] = make_float2(acc[n8][2], acc[n8][3]);
    }
}

// ---------------------------------------------------------------------------
extern "C" void kernel_launch(void* const* d_in, const int* in_sizes, int n_in,
                              void* d_out, int out_size)
{
    const float* X    = (const float*)d_in[0];   // (B,S,H)
    const int*   mask = (const int*)  d_in[1];   // (B,S,1)
    const float* tf   = (const float*)d_in[2];   // (B,S,1)
    const float* W1   = (const float*)d_in[3];
    const float* b1   = (const float*)d_in[4];
    const float* W2   = (const float*)d_in[5];
    const float* b2   = (const float*)d_in[6];
    const float* W3   = (const float*)d_in[7];
    float* out = (float*)d_out;                  // (B,K,H)

    cudaFuncSetAttribute(mlp_softk_kernel,
                         cudaFuncAttributeMaxDynamicSharedMemorySize, SM_BYTES);
    cudaFuncSetAttribute(out_gemm_kernel,
                         cudaFuncAttributeMaxDynamicSharedMemorySize, K2_BYTES);

    prep_kernel<<<66, 256>>>(W1, W2, W3);
    mlp_softk_kernel<<<NBLK, 256, SM_BYTES>>>(X, mask, b1, b2);
    out_gemm_kernel<<<dim3(B_, 2), 128, K2_BYTES>>>(tf, out);
}

// round 11
// speedup vs baseline: 1.4342x; 1.3357x over previous
#include <cuda_runtime.h>
#include <cuda_fp16.h>
#include <math.h>
#include <stdint.h>

#define B_  512
#define S_  200
#define H_  256
#define K_  16
#define ROWS (B_*S_)          // 102400
#define TM  128               // rows per CTA (kernel 1)
#define NBLK (ROWS/TM)        // 800 (max tiles; most exit early)

// ---- kernel-1 smem layout (words) ----
#define ASTW  132
#define CBSTW 36
#define A_WORDS  (128*ASTW)
#define BC_OFF   A_WORDS
#define BC_ONE   (256*CBSTW)
#define W3_OFF   (BC_OFF + 2*BC_ONE)
#define W3STW 132
#define RID_OFF  (W3_OFF + 16*W3STW)      // 37440 ; 128 row indices
#define SM_WORDS (RID_OFF + 128)
#define SM_BYTES (SM_WORDS*4)             // 150272

// ---- kernel-2 smem layout (words): per-CTA = one h-half of one batch ----
#define XCH    64
#define XSTW2  68
#define XBUF2  (XCH*XSTW2)
#define DS2_OFF (2*XBUF2)
#define DST2   132
#define AFST   17
#define AF2_OFF (DS2_OFF + 16*DST2)
#define TF2_OFF (AF2_OFF + S_*AFST)
#define MK2_OFF (TF2_OFF + S_)
#define IK2_OFF (MK2_OFF + 16)
#define K2_WORDS (IK2_OFF + 16)
#define K2_BYTES (K2_WORDS*4)             // 57792

// scratch
__device__ float    g_A[ROWS * K_];          // masked K-softmax logits
__device__ uint32_t g_Xh[(ROWS + 56) * 128]; // X fp16 [row][h]; dead rows stay 0
__device__ uint32_t g_Wh[2 * 32768];         // W1,W2 fp16 [l][c4][n256][kl64]
__device__ uint32_t g_Wh3[16 * 128];         // W3 fp16 [n16][k256]
__device__ int      g_rows[ROWS];            // compacted unmasked row ids
__device__ int      g_cnt;                   // number of unmasked rows

__device__ __forceinline__ uint32_t smem_u32(const void* p) {
    uint32_t a;
    asm("{ .reg .u64 t; cvta.to.shared.u64 t, %1; cvt.u32.u64 %0, t; }"
        : "=r"(a) : "l"(p));
    return a;
}
__device__ __forceinline__ uint32_t pack_h2(float lo, float hi) {
    const __half2 h = __floats2half2_rn(lo, hi);
    return *(const uint32_t*)&h;
}
__device__ __forceinline__ void mma16(float c[4], const uint32_t a[4],
                                      uint32_t b0, uint32_t b1) {
    asm("mma.sync.aligned.m16n8k16.row.col.f32.f16.f16.f32 "
        "{%0,%1,%2,%3}, {%4,%5,%6,%7}, {%8,%9}, {%0,%1,%2,%3};"
        : "+f"(c[0]), "+f"(c[1]), "+f"(c[2]), "+f"(c[3])
        : "r"(a[0]), "r"(a[1]), "r"(a[2]), "r"(a[3]), "r"(b0), "r"(b1));
}
__device__ __forceinline__ void ldsm_x4(uint32_t& r0, uint32_t& r1,
                                        uint32_t& r2, uint32_t& r3, uint32_t addr) {
    asm volatile("ldmatrix.sync.aligned.m8n8.x4.shared.b16 {%0,%1,%2,%3}, [%4];"
                 : "=r"(r0), "=r"(r1), "=r"(r2), "=r"(r3) : "r"(addr));
}
__device__ __forceinline__ void ldsm_x4_t(uint32_t& r0, uint32_t& r1,
                                          uint32_t& r2, uint32_t& r3, uint32_t addr) {
    asm volatile("ldmatrix.sync.aligned.m8n8.x4.trans.shared.b16 {%0,%1,%2,%3}, [%4];"
                 : "=r"(r0), "=r"(r1), "=r"(r2), "=r"(r3) : "r"(addr));
}
__device__ __forceinline__ void cpasync16(uint32_t dst, const void* src) {
    asm volatile("cp.async.cg.shared.global [%0], [%1], 16;" :: "r"(dst), "l"(src));
}
#define CP_COMMIT() asm volatile("cp.async.commit_group;" ::: "memory")
#define CP_WAIT0()  asm volatile("cp.async.wait_group 0;" ::: "memory")

// ---------------------------------------------------------------------------
// Reset: zero the compaction counter (must run before prep each launch)
// ---------------------------------------------------------------------------
__global__ void reset_kernel() { if (threadIdx.x == 0) g_cnt = 0; }

// ---------------------------------------------------------------------------
// Prep: blocks 0-65 convert weights; blocks 66-465 compact unmasked rows and
// write the -2500 default for masked rows.
// ---------------------------------------------------------------------------
__global__ void prep_kernel(const float* __restrict__ W1,
                            const float* __restrict__ W2,
                            const float* __restrict__ W3,
                            const int*   __restrict__ mask)
{
    const int tid = threadIdx.x;
    if (blockIdx.x < 66) {
        const int i = blockIdx.x * 256 + tid;
        if (i < 16384) {
            const int kl8 = i & 7;
            const int n   = (i >> 3) & 255;
            const int c   = (i >> 11) & 3;
            const int l   = i >> 13;
            const float* W = l ? W2 : W1;
            const int kbase = c * 64 + kl8 * 8;
            uint4 o;
            o.x = pack_h2(W[(size_t)(kbase+0)*H_ + n], W[(size_t)(kbase+1)*H_ + n]);
            o.y = pack_h2(W[(size_t)(kbase+2)*H_ + n], W[(size_t)(kbase+3)*H_ + n]);
            o.z = pack_h2(W[(size_t)(kbase+4)*H_ + n], W[(size_t)(kbase+5)*H_ + n]);
            o.w = pack_h2(W[(size_t)(kbase+6)*H_ + n], W[(size_t)(kbase+7)*H_ + n]);
            *(uint4*)&g_Wh[(size_t)i * 4] = o;
        } else if (i < 16384 + 512) {
            const int j  = i - 16384;
            const int n  = j >> 5;
            const int k8 = (j & 31) * 8;
            uint4 o;
            o.x = pack_h2(W3[(size_t)(k8+0)*K_ + n], W3[(size_t)(k8+1)*K_ + n]);
            o.y = pack_h2(W3[(size_t)(k8+2)*K_ + n], W3[(size_t)(k8+3)*K_ + n]);
            o.z = pack_h2(W3[(size_t)(k8+4)*K_ + n], W3[(size_t)(k8+5)*K_ + n]);
            o.w = pack_h2(W3[(size_t)(k8+6)*K_ + n], W3[(size_t)(k8+7)*K_ + n]);
            *(uint4*)&g_Wh3[(size_t)j * 4] = o;
        }
    } else {
        const int row  = (blockIdx.x - 66) * 256 + tid;
        const int lane = tid & 31;
        const bool mk  = (mask[row] != 0);
        const unsigned bal = __ballot_sync(0xffffffffu, mk);
        int base = 0;
        if (lane == 0) base = atomicAdd(&g_cnt, __popc(bal));
        base = __shfl_sync(0xffffffffu, base, 0);
        if (mk) {
            g_rows[base + __popc(bal & ((1u << lane) - 1u))] = row;
        } else {
            const float4 m4 = make_float4(-2500.f, -2500.f, -2500.f, -2500.f);
            float4* gp = (float4*)&g_A[(size_t)row * K_];
            gp[0] = m4; gp[1] = m4; gp[2] = m4; gp[3] = m4;
        }
    }
}

// ---------------------------------------------------------------------------
// Kernel 1: fp16 mma.sync MLP on COMPACTED rows + X fp16 export
// ---------------------------------------------------------------------------
__device__ __forceinline__ void prefetch_chunk(uint32_t sb, int tid,
                                               int layer, int cc, int buf) {
    const uint32_t* src = g_Wh + (size_t)(layer * 4 + cc) * 8192 + tid * 32;
    const uint32_t  dst = sb + (uint32_t)(BC_OFF + buf * BC_ONE + tid * CBSTW) * 4;
    #pragma unroll
    for (int j = 0; j < 8; j++) cpasync16(dst + j * 16, src + j * 4);
}
__device__ __forceinline__ void prefetch_w3(uint32_t sb, int tid) {
    #pragma unroll
    for (int q = 0; q < 2; q++) {
        const int i = tid * 2 + q;
        const int n = i >> 5, kk = i & 31;
        cpasync16(sb + (uint32_t)(W3_OFF + n * W3STW + kk * 4) * 4,
                  g_Wh3 + (size_t)i * 4);
    }
}

__global__ __launch_bounds__(256, 1)
void mlp_softk_kernel(const float* __restrict__ X,
                      const int*   __restrict__ mask,
                      const float* __restrict__ b1,
                      const float* __restrict__ b2)
{
    const int total = g_cnt;                 // unmasked row count
    const int row0  = blockIdx.x * TM;
    if (row0 >= total) return;
    const int nrows = min(TM, total - row0);

    extern __shared__ uint32_t smu[];
    const uint32_t sb = smem_u32(smu);
    int* rid = (int*)(smu + RID_OFF);
    const int tid  = threadIdx.x;
    const int wid  = tid >> 5;
    const int lane = tid & 31;
    const int g    = lane >> 2;
    const int tq   = lane & 3;

    prefetch_chunk(sb, tid, 0, 0, 0);
    CP_COMMIT();

    if (tid < 128) rid[tid] = g_rows[row0 + min(tid, nrows - 1)];
    __syncthreads();

    // gather X rows -> A (fp16) + export fp16 X to g_Xh
    #pragma unroll 4
    for (int it = 0; it < 32; it++) {
        const int idx = tid + it * 256;
        const int r = idx >> 6, c4 = (idx & 63) * 4;
        const int grow = rid[r];
        const float4 v = __ldg((const float4*)(X + (size_t)grow * H_ + c4));
        uint2 o;
        o.x = pack_h2(v.x, v.y);
        o.y = pack_h2(v.z, v.w);
        *(uint2*)&smu[r * ASTW + (c4 >> 1)] = o;
        *(uint2*)&g_Xh[(size_t)grow * 128 + (c4 >> 1)] = o;
    }

    const int wm = wid & 3;
    const int wn = wid >> 2;

    const int q8 = lane >> 3;
    const int r8 = lane & 7;
    int a_lane_off[2];
    #pragma unroll
    for (int mt = 0; mt < 2; mt++)
        a_lane_off[mt] = (wm * 32 + mt * 16 + (q8 & 1) * 8 + r8) * ASTW + (q8 >> 1) * 4;
    const int b_lane_row = (q8 >> 1) * 8 + r8;
    const int b_lane_kw  = (q8 & 1) * 4;

    #pragma unroll 1
    for (int layer = 0; layer < 2; layer++) {
        const float* bg = layer ? b2 : b1;

        float acc[2][16][4];
        #pragma unroll
        for (int mt = 0; mt < 2; mt++)
            #pragma unroll
            for (int n8 = 0; n8 < 16; n8++)
                #pragma unroll
                for (int i = 0; i < 4; i++) acc[mt][n8][i] = 0.0f;

        #pragma unroll 1
        for (int cc = 0; cc < 4; cc++) {
            CP_WAIT0();
            __syncthreads();

            if (layer == 1 && cc == 3) prefetch_w3(sb, tid);
            else {
                const int nl = (cc == 3) ? 1 : layer;
                const int nc = (cc == 3) ? 0 : cc + 1;
                prefetch_chunk(sb, tid, nl, nc, (cc + 1) & 1);
            }
            CP_COMMIT();

            const uint32_t bbase = sb + (uint32_t)(BC_OFF + (cc & 1) * BC_ONE) * 4;
            #pragma unroll
            for (int ks = 0; ks < 4; ks++) {
                const int kw  = (cc * 64 + ks * 16) >> 1;
                const int klw = ks * 8;
                uint32_t a[2][4];
                #pragma unroll
                for (int mt = 0; mt < 2; mt++)
                    ldsm_x4(a[mt][0], a[mt][1], a[mt][2], a[mt][3],
                            sb + (uint32_t)(a_lane_off[mt] + kw) * 4);
                #pragma unroll
                for (int p = 0; p < 8; p++) {
                    const int nrow = wn * 128 + p * 16 + b_lane_row;
                    uint32_t b0a, b1a, b0b, b1b;
                    ldsm_x4(b0a, b1a, b0b, b1b,
                            bbase + (uint32_t)(nrow * CBSTW + klw + b_lane_kw) * 4);
                    mma16(acc[0][2*p    ], a[0], b0a, b1a);
                    mma16(acc[1][2*p    ], a[1], b0a, b1a);
                    mma16(acc[0][2*p + 1], a[0], b0b, b1b);
                    mma16(acc[1][2*p + 1], a[1], b0b, b1b);
                }
            }
        }
        __syncthreads();

        #pragma unroll
        for (int mt = 0; mt < 2; mt++) {
            const int r = wm * 32 + mt * 16 + g;
            #pragma unroll
            for (int n8 = 0; n8 < 16; n8++) {
                const int c = wn * 128 + n8 * 8 + 2 * tq;
                const float2 bb = *(const float2*)&bg[c];
                smu[(r    ) * ASTW + (c >> 1)] =
                    pack_h2(fmaxf(acc[mt][n8][0] + bb.x, 0.f),
                            fmaxf(acc[mt][n8][1] + bb.y, 0.f));
                smu[(r + 8) * ASTW + (c >> 1)] =
                    pack_h2(fmaxf(acc[mt][n8][2] + bb.x, 0.f),
                            fmaxf(acc[mt][n8][3] + bb.y, 0.f));
            }
        }
    }

    CP_WAIT0();
    __syncthreads();

    // layer 3
    float acc3[2][4];
    #pragma unroll
    for (int n8 = 0; n8 < 2; n8++)
        #pragma unroll
        for (int i = 0; i < 4; i++) acc3[n8][i] = 0.0f;

    {
        const uint32_t* Bu3 = smu + W3_OFF;
        const int r = wid * 16 + g;
        #pragma unroll 4
        for (int ks = 0; ks < 16; ks++) {
            const int kw = ks * 8;
            uint32_t a[4];
            a[0] = smu[(r    ) * ASTW + kw + tq];
            a[1] = smu[(r + 8) * ASTW + kw + tq];
            a[2] = smu[(r    ) * ASTW + kw + tq + 4];
            a[3] = smu[(r + 8) * ASTW + kw + tq + 4];
            #pragma unroll
            for (int n8 = 0; n8 < 2; n8++) {
                const uint32_t b0 = Bu3[(n8 * 8 + g) * W3STW + kw + tq];
                const uint32_t b1v = Bu3[(n8 * 8 + g) * W3STW + kw + tq + 4];
                mma16(acc3[n8], a, b0, b1v);
            }
        }
    }

    // softmax over K=16 per row, mask re-check (tile-tail duplicates), store
    #pragma unroll
    for (int p = 0; p < 2; p++) {
        const int rr  = wid * 16 + g + p * 8;
        const int row = rid[rr];
        float v0 = acc3[0][2 * p], v1 = acc3[0][2 * p + 1];
        float v2 = acc3[1][2 * p], v3 = acc3[1][2 * p + 1];
        float m = fmaxf(fmaxf(v0, v1), fmaxf(v2, v3));
        m = fmaxf(m, __shfl_xor_sync(0xffffffffu, m, 1));
        m = fmaxf(m, __shfl_xor_sync(0xffffffffu, m, 2));
        const float e0 = expf(v0 - m), e1 = expf(v1 - m);
        const float e2 = expf(v2 - m), e3 = expf(v3 - m);
        float ssum = e0 + e1 + e2 + e3;
        ssum += __shfl_xor_sync(0xffffffffu, ssum, 1);
        ssum += __shfl_xor_sync(0xffffffffu, ssum, 2);
        const float inv = 0.25f / ssum;
        const bool mk = (mask[row] != 0);
        float2 oa, ob;
        oa.x = mk ? e0 * inv : -2500.0f;
        oa.y = mk ? e1 * inv : -2500.0f;
        ob.x = mk ? e2 * inv : -2500.0f;
        ob.y = mk ? e3 * inv : -2500.0f;
        *(float2*)&g_A[(size_t)row * K_ + 2 * tq]     = oa;
        *(float2*)&g_A[(size_t)row * K_ + 8 + 2 * tq] = ob;
    }
}

// ---------------------------------------------------------------------------
// Kernel 2: grid (512, 2) — CTA = (batch, h-half). (round-10 version)
// ---------------------------------------------------------------------------
__global__ __launch_bounds__(128, 4)
void out_gemm_kernel(const float* __restrict__ tf,
                     float*       __restrict__ out)
{
    extern __shared__ uint32_t smu[];
    const uint32_t sb = smem_u32(smu);
    const int tid  = threadIdx.x;
    const int w    = tid >> 5;
    const int lane = tid & 31;
    const int g    = lane >> 2;
    const int tq   = lane & 3;
    const int b    = blockIdx.x;
    const int hb   = blockIdx.y;

    {
        const uint32_t* src = g_Xh + (size_t)(b * S_) * 128 + hb * 64;
        #pragma unroll
        for (int j = 0; j < 8; j++) {
            const int line = tid + j * 128;
            const int r = line >> 4, lw = line & 15;
            cpasync16(sb + (uint32_t)(r * XSTW2 + lw * 4) * 4,
                      src + (size_t)r * 128 + lw * 4);
        }
        CP_COMMIT();
    }

    float* Af = (float*)(smu + AF2_OFF);
    float* Tf = (float*)(smu + TF2_OFF);
    float* Mk = (float*)(smu + MK2_OFF);
    float* Ik = (float*)(smu + IK2_OFF);

    for (int idx = tid; idx < S_ * K_; idx += 128) {
        const int s = idx >> 4, k = idx & 15;
        Af[s * AFST + k] = g_A[(size_t)b * S_ * K_ + idx];
    }
    for (int idx = tid; idx < S_; idx += 128)
        Tf[idx] = tf[b * S_ + idx];
    __syncthreads();

    #pragma unroll
    for (int kk = 0; kk < 4; kk++) {
        const int k = w + kk * 4;
        float m = -1e30f;
        for (int s = lane; s < S_; s += 32) m = fmaxf(m, Af[s * AFST + k]);
        #pragma unroll
        for (int o = 16; o; o >>= 1) m = fmaxf(m, __shfl_xor_sync(0xffffffffu, m, o));
        float ss = 0.0f;
        for (int s = lane; s < S_; s += 32) ss += expf(Af[s * AFST + k] - m);
        #pragma unroll
        for (int o = 16; o; o >>= 1) ss += __shfl_xor_sync(0xffffffffu, ss, o);
        if (lane == 0) { Mk[k] = m; Ik[k] = 1.0f / ss; }
    }
    __syncthreads();

    for (int idx = tid; idx < 16 * 128; idx += 128) {
        const int k = idx >> 7, sw = idx & 127, s0 = sw * 2;
        float v0 = 0.0f, v1 = 0.0f;
        if (s0     < S_) v0 = expf(Af[s0 * AFST + k]       - Mk[k]) * Ik[k] * Tf[s0];
        if (s0 + 1 < S_) v1 = expf(Af[(s0 + 1) * AFST + k] - Mk[k]) * Ik[k] * Tf[s0 + 1];
        smu[DS2_OFF + k * DST2 + sw] = pack_h2(v0, v1);
    }

    float acc[4][4];
    #pragma unroll
    for (int n8 = 0; n8 < 4; n8++)
        #pragma unroll
        for (int i = 0; i < 4; i++) acc[n8][i] = 0.0f;

    const int q8 = lane >> 3, r8 = lane & 7;
    const int a_off  = DS2_OFF + ((q8 & 1) * 8 + r8) * DST2 + (q8 >> 1) * 4;
    const int b_srow = (q8 & 1) * 8 + r8;
    const int b_hw   = w * 16 + (q8 >> 1) * 4;

    #pragma unroll 1
    for (int c = 0; c < 4; c++) {
        CP_WAIT0();
        __syncthreads();
        if (c < 3) {
            const uint32_t* src = g_Xh + (size_t)(b * S_ + (c + 1) * XCH) * 128 + hb * 64;
            const uint32_t dbuf = sb + (uint32_t)(((c + 1) & 1) * XBUF2) * 4;
            #pragma unroll
            for (int j = 0; j < 8; j++) {
                const int line = tid + j * 128;
                const int r = line >> 4, lw = line & 15;
                cpasync16(dbuf + (uint32_t)(r * XSTW2 + lw * 4) * 4,
                          src + (size_t)r * 128 + lw * 4);
            }
            CP_COMMIT();
        }
        const uint32_t xbuf = sb + (uint32_t)((c & 1) * XBUF2) * 4;
        #pragma unroll
        for (int ks = 0; ks < 4; ks++) {
            uint32_t a[4];
            ldsm_x4(a[0], a[1], a[2], a[3],
                    sb + (uint32_t)(a_off + c * 32 + ks * 8) * 4);
            #pragma unroll
            for (int p = 0; p < 2; p++) {
                uint32_t r0, r1, r2, r3;
                ldsm_x4_t(r0, r1, r2, r3,
                    xbuf + (uint32_t)((ks * 16 + b_srow) * XSTW2 + b_hw + p * 8) * 4);
                mma16(acc[2 * p    ], a, r0, r1);
                mma16(acc[2 * p + 1], a, r2, r3);
            }
        }
    }

    float* ob = out + (size_t)b * K_ * H_ + hb * 128;
    #pragma unroll
    for (int n8 = 0; n8 < 4; n8++) {
        const int h = w * 32 + n8 * 8 + 2 * tq;
        *(float2*)&ob[(g    ) * H_ + h] = make_float2(acc[n8][0], acc[n8][1]);
        *(float2*)&ob[(g + 8) * H_ + h] = make_float2(acc[n8][2], acc[n8][3]);
    }
}

// ---------------------------------------------------------------------------
extern "C" void kernel_launch(void* const* d_in, const int* in_sizes, int n_in,
                              void* d_out, int out_size)
{
    const float* X    = (const float*)d_in[0];   // (B,S,H)
    const int*   mask = (const int*)  d_in[1];   // (B,S,1)
    const float* tf   = (const float*)d_in[2];   // (B,S,1)
    const float* W1   = (const float*)d_in[3];
    const float* b1   = (const float*)d_in[4];
    const float* W2   = (const float*)d_in[5];
    const float* b2   = (const float*)d_in[6];
    const float* W3   = (const float*)d_in[7];
    float* out = (float*)d_out;                  // (B,K,H)

    cudaFuncSetAttribute(mlp_softk_kernel,
                         cudaFuncAttributeMaxDynamicSharedMemorySize, SM_BYTES);
    cudaFuncSetAttribute(out_gemm_kernel,
                         cudaFuncAttributeMaxDynamicSharedMemorySize, K2_BYTES);

    reset_kernel<<<1, 32>>>();
    prep_kernel<<<466, 256>>>(W1, W2, W3, mask);
    mlp_softk_kernel<<<NBLK, 256, SM_BYTES>>>(X, mask, b1, b2);
    out_gemm_kernel<<<dim3(B_, 2), 128, K2_BYTES>>>(tf, out);
}

// round 12
// speedup vs baseline: 1.4986x; 1.0449x over previous
#include <cuda_runtime.h>
#include <cuda_fp16.h>
#include <math.h>
#include <stdint.h>

#define B_  512
#define S_  200
#define H_  256
#define K_  16
#define ROWS (B_*S_)          // 102400
#define TM  128               // rows per CTA (kernel 1)
#define NBLK (ROWS/TM)        // 800 (max tiles; ~half exit early)

// ---- kernel-1 smem layout (words) ----
#define ASTW  132
#define CBSTW 36
#define A_WORDS  (128*ASTW)
#define BC_OFF   A_WORDS
#define BC_ONE   (256*CBSTW)
#define W3_OFF   (BC_OFF + 2*BC_ONE)
#define W3STW 132
#define RID_OFF  (W3_OFF + 16*W3STW)
#define SM_WORDS (RID_OFF + 128)
#define SM_BYTES (SM_WORDS*4)             // 150272

// ---- kernel-2 smem layout (words): one CTA per batch, 256 threads ----
#define XCH    64                         // s-rows per X chunk
#define XSTW2  132                        // X chunk row stride (256 h fp16 + pad)
#define XBUF2  (XCH*XSTW2)                // 8448
#define DS2_OFF (2*XBUF2)                 // 16896 ; Ds: 16 k x 256 s fp16
#define DST2   132
#define AFST   17                         // Af row stride - conflict-free
#define AF2_OFF (DS2_OFF + 16*DST2)       // 19008
#define TF2_OFF (AF2_OFF + S_*AFST)       // 22408
#define IK2_OFF (TF2_OFF + S_)            // 22608
#define K2_WORDS (IK2_OFF + 16)           // 22624
#define K2_BYTES (K2_WORDS*4)             // 90496 -> 2 CTAs/SM

// scratch
__device__ float    g_A[ROWS * K_];          // masked K-softmax logits
__device__ uint32_t g_Xh[(ROWS + 56) * 128]; // X fp16 [row][h]; dead rows stay 0
__device__ uint32_t g_Wh[2 * 32768];         // W1,W2 fp16 [l][c4][n256][kl64]
__device__ uint32_t g_Wh3[16 * 128];         // W3 fp16 [n16][k256]
__device__ int      g_rows[ROWS];            // compacted unmasked row ids
__device__ int      g_cnt;                   // number of unmasked rows

__device__ __forceinline__ uint32_t smem_u32(const void* p) {
    uint32_t a;
    asm("{ .reg .u64 t; cvta.to.shared.u64 t, %1; cvt.u32.u64 %0, t; }"
        : "=r"(a) : "l"(p));
    return a;
}
__device__ __forceinline__ uint32_t pack_h2(float lo, float hi) {
    const __half2 h = __floats2half2_rn(lo, hi);
    return *(const uint32_t*)&h;
}
__device__ __forceinline__ void mma16(float c[4], const uint32_t a[4],
                                      uint32_t b0, uint32_t b1) {
    asm("mma.sync.aligned.m16n8k16.row.col.f32.f16.f16.f32 "
        "{%0,%1,%2,%3}, {%4,%5,%6,%7}, {%8,%9}, {%0,%1,%2,%3};"
        : "+f"(c[0]), "+f"(c[1]), "+f"(c[2]), "+f"(c[3])
        : "r"(a[0]), "r"(a[1]), "r"(a[2]), "r"(a[3]), "r"(b0), "r"(b1));
}
__device__ __forceinline__ void ldsm_x4(uint32_t& r0, uint32_t& r1,
                                        uint32_t& r2, uint32_t& r3, uint32_t addr) {
    asm volatile("ldmatrix.sync.aligned.m8n8.x4.shared.b16 {%0,%1,%2,%3}, [%4];"
                 : "=r"(r0), "=r"(r1), "=r"(r2), "=r"(r3) : "r"(addr));
}
__device__ __forceinline__ void ldsm_x4_t(uint32_t& r0, uint32_t& r1,
                                          uint32_t& r2, uint32_t& r3, uint32_t addr) {
    asm volatile("ldmatrix.sync.aligned.m8n8.x4.trans.shared.b16 {%0,%1,%2,%3}, [%4];"
                 : "=r"(r0), "=r"(r1), "=r"(r2), "=r"(r3) : "r"(addr));
}
__device__ __forceinline__ void cpasync16(uint32_t dst, const void* src) {
    asm volatile("cp.async.cg.shared.global [%0], [%1], 16;" :: "r"(dst), "l"(src));
}
#define CP_COMMIT() asm volatile("cp.async.commit_group;" ::: "memory")
#define CP_WAIT0()  asm volatile("cp.async.wait_group 0;" ::: "memory")

// ---------------------------------------------------------------------------
// Prep: blocks 0-65 convert weights; blocks 66-465 compact unmasked rows
// ---------------------------------------------------------------------------
__global__ void prep_kernel(const float* __restrict__ W1,
                            const float* __restrict__ W2,
                            const float* __restrict__ W3,
                            const int*   __restrict__ mask)
{
    const int tid = threadIdx.x;
    if (blockIdx.x < 66) {
        const int i = blockIdx.x * 256 + tid;
        if (i < 16384) {
            const int kl8 = i & 7;
            const int n   = (i >> 3) & 255;
            const int c   = (i >> 11) & 3;
            const int l   = i >> 13;
            const float* W = l ? W2 : W1;
            const int kbase = c * 64 + kl8 * 8;
            uint4 o;
            o.x = pack_h2(W[(size_t)(kbase+0)*H_ + n], W[(size_t)(kbase+1)*H_ + n]);
            o.y = pack_h2(W[(size_t)(kbase+2)*H_ + n], W[(size_t)(kbase+3)*H_ + n]);
            o.z = pack_h2(W[(size_t)(kbase+4)*H_ + n], W[(size_t)(kbase+5)*H_ + n]);
            o.w = pack_h2(W[(size_t)(kbase+6)*H_ + n], W[(size_t)(kbase+7)*H_ + n]);
            *(uint4*)&g_Wh[(size_t)i * 4] = o;
        } else if (i < 16384 + 512) {
            const int j  = i - 16384;
            const int n  = j >> 5;
            const int k8 = (j & 31) * 8;
            uint4 o;
            o.x = pack_h2(W3[(size_t)(k8+0)*K_ + n], W3[(size_t)(k8+1)*K_ + n]);
            o.y = pack_h2(W3[(size_t)(k8+2)*K_ + n], W3[(size_t)(k8+3)*K_ + n]);
            o.z = pack_h2(W3[(size_t)(k8+4)*K_ + n], W3[(size_t)(k8+5)*K_ + n]);
            o.w = pack_h2(W3[(size_t)(k8+6)*K_ + n], W3[(size_t)(k8+7)*K_ + n]);
            *(uint4*)&g_Wh3[(size_t)j * 4] = o;
        }
    } else {
        const int row  = (blockIdx.x - 66) * 256 + tid;
        const int lane = tid & 31;
        const bool mk  = (mask[row] != 0);
        const unsigned bal = __ballot_sync(0xffffffffu, mk);
        int base = 0;
        if (lane == 0) base = atomicAdd(&g_cnt, __popc(bal));
        base = __shfl_sync(0xffffffffu, base, 0);
        if (mk) {
            g_rows[base + __popc(bal & ((1u << lane) - 1u))] = row;
        } else {
            const float4 m4 = make_float4(-2500.f, -2500.f, -2500.f, -2500.f);
            float4* gp = (float4*)&g_A[(size_t)row * K_];
            gp[0] = m4; gp[1] = m4; gp[2] = m4; gp[3] = m4;
        }
    }
}

// ---------------------------------------------------------------------------
// Kernel 1: fp16 mma.sync MLP on COMPACTED rows + X fp16 export (unchanged)
// ---------------------------------------------------------------------------
__device__ __forceinline__ void prefetch_chunk(uint32_t sb, int tid,
                                               int layer, int cc, int buf) {
    const uint32_t* src = g_Wh + (size_t)(layer * 4 + cc) * 8192 + tid * 32;
    const uint32_t  dst = sb + (uint32_t)(BC_OFF + buf * BC_ONE + tid * CBSTW) * 4;
    #pragma unroll
    for (int j = 0; j < 8; j++) cpasync16(dst + j * 16, src + j * 4);
}
__device__ __forceinline__ void prefetch_w3(uint32_t sb, int tid) {
    #pragma unroll
    for (int q = 0; q < 2; q++) {
        const int i = tid * 2 + q;
        const int n = i >> 5, kk = i & 31;
        cpasync16(sb + (uint32_t)(W3_OFF + n * W3STW + kk * 4) * 4,
                  g_Wh3 + (size_t)i * 4);
    }
}

__global__ __launch_bounds__(256, 1)
void mlp_softk_kernel(const float* __restrict__ X,
                      const int*   __restrict__ mask,
                      const float* __restrict__ b1,
                      const float* __restrict__ b2)
{
    const int total = g_cnt;
    const int row0  = blockIdx.x * TM;
    if (row0 >= total) return;
    const int nrows = min(TM, total - row0);

    extern __shared__ uint32_t smu[];
    const uint32_t sb = smem_u32(smu);
    int* rid = (int*)(smu + RID_OFF);
    const int tid  = threadIdx.x;
    const int wid  = tid >> 5;
    const int lane = tid & 31;
    const int g    = lane >> 2;
    const int tq   = lane & 3;

    prefetch_chunk(sb, tid, 0, 0, 0);
    CP_COMMIT();

    if (tid < 128) rid[tid] = g_rows[row0 + min(tid, nrows - 1)];
    __syncthreads();

    #pragma unroll 4
    for (int it = 0; it < 32; it++) {
        const int idx = tid + it * 256;
        const int r = idx >> 6, c4 = (idx & 63) * 4;
        const int grow = rid[r];
        const float4 v = __ldg((const float4*)(X + (size_t)grow * H_ + c4));
        uint2 o;
        o.x = pack_h2(v.x, v.y);
        o.y = pack_h2(v.z, v.w);
        *(uint2*)&smu[r * ASTW + (c4 >> 1)] = o;
        *(uint2*)&g_Xh[(size_t)grow * 128 + (c4 >> 1)] = o;
    }

    const int wm = wid & 3;
    const int wn = wid >> 2;

    const int q8 = lane >> 3;
    const int r8 = lane & 7;
    int a_lane_off[2];
    #pragma unroll
    for (int mt = 0; mt < 2; mt++)
        a_lane_off[mt] = (wm * 32 + mt * 16 + (q8 & 1) * 8 + r8) * ASTW + (q8 >> 1) * 4;
    const int b_lane_row = (q8 >> 1) * 8 + r8;
    const int b_lane_kw  = (q8 & 1) * 4;

    #pragma unroll 1
    for (int layer = 0; layer < 2; layer++) {
        const float* bg = layer ? b2 : b1;

        float acc[2][16][4];
        #pragma unroll
        for (int mt = 0; mt < 2; mt++)
            #pragma unroll
            for (int n8 = 0; n8 < 16; n8++)
                #pragma unroll
                for (int i = 0; i < 4; i++) acc[mt][n8][i] = 0.0f;

        #pragma unroll 1
        for (int cc = 0; cc < 4; cc++) {
            CP_WAIT0();
            __syncthreads();

            if (layer == 1 && cc == 3) prefetch_w3(sb, tid);
            else {
                const int nl = (cc == 3) ? 1 : layer;
                const int nc = (cc == 3) ? 0 : cc + 1;
                prefetch_chunk(sb, tid, nl, nc, (cc + 1) & 1);
            }
            CP_COMMIT();

            const uint32_t bbase = sb + (uint32_t)(BC_OFF + (cc & 1) * BC_ONE) * 4;
            #pragma unroll
            for (int ks = 0; ks < 4; ks++) {
                const int kw  = (cc * 64 + ks * 16) >> 1;
                const int klw = ks * 8;
                uint32_t a[2][4];
                #pragma unroll
                for (int mt = 0; mt < 2; mt++)
                    ldsm_x4(a[mt][0], a[mt][1], a[mt][2], a[mt][3],
                            sb + (uint32_t)(a_lane_off[mt] + kw) * 4);
                #pragma unroll
                for (int p = 0; p < 8; p++) {
                    const int nrow = wn * 128 + p * 16 + b_lane_row;
                    uint32_t b0a, b1a, b0b, b1b;
                    ldsm_x4(b0a, b1a, b0b, b1b,
                            bbase + (uint32_t)(nrow * CBSTW + klw + b_lane_kw) * 4);
                    mma16(acc[0][2*p    ], a[0], b0a, b1a);
                    mma16(acc[1][2*p    ], a[1], b0a, b1a);
                    mma16(acc[0][2*p + 1], a[0], b0b, b1b);
                    mma16(acc[1][2*p + 1], a[1], b0b, b1b);
                }
            }
        }
        __syncthreads();

        #pragma unroll
        for (int mt = 0; mt < 2; mt++) {
            const int r = wm * 32 + mt * 16 + g;
            #pragma unroll
            for (int n8 = 0; n8 < 16; n8++) {
                const int c = wn * 128 + n8 * 8 + 2 * tq;
                const float2 bb = *(const float2*)&bg[c];
                smu[(r    ) * ASTW + (c >> 1)] =
                    pack_h2(fmaxf(acc[mt][n8][0] + bb.x, 0.f),
                            fmaxf(acc[mt][n8][1] + bb.y, 0.f));
                smu[(r + 8) * ASTW + (c >> 1)] =
                    pack_h2(fmaxf(acc[mt][n8][2] + bb.x, 0.f),
                            fmaxf(acc[mt][n8][3] + bb.y, 0.f));
            }
        }
    }

    CP_WAIT0();
    __syncthreads();

    float acc3[2][4];
    #pragma unroll
    for (int n8 = 0; n8 < 2; n8++)
        #pragma unroll
        for (int i = 0; i < 4; i++) acc3[n8][i] = 0.0f;

    {
        const uint32_t* Bu3 = smu + W3_OFF;
        const int r = wid * 16 + g;
        #pragma unroll 4
        for (int ks = 0; ks < 16; ks++) {
            const int kw = ks * 8;
            uint32_t a[4];
            a[0] = smu[(r    ) * ASTW + kw + tq];
            a[1] = smu[(r + 8) * ASTW + kw + tq];
            a[2] = smu[(r    ) * ASTW + kw + tq + 4];
            a[3] = smu[(r + 8) * ASTW + kw + tq + 4];
            #pragma unroll
            for (int n8 = 0; n8 < 2; n8++) {
                const uint32_t b0 = Bu3[(n8 * 8 + g) * W3STW + kw + tq];
                const uint32_t b1v = Bu3[(n8 * 8 + g) * W3STW + kw + tq + 4];
                mma16(acc3[n8], a, b0, b1v);
            }
        }
    }

    #pragma unroll
    for (int p = 0; p < 2; p++) {
        const int rr  = wid * 16 + g + p * 8;
        const int row = rid[rr];
        float v0 = acc3[0][2 * p], v1 = acc3[0][2 * p + 1];
        float v2 = acc3[1][2 * p], v3 = acc3[1][2 * p + 1];
        float m = fmaxf(fmaxf(v0, v1), fmaxf(v2, v3));
        m = fmaxf(m, __shfl_xor_sync(0xffffffffu, m, 1));
        m = fmaxf(m, __shfl_xor_sync(0xffffffffu, m, 2));
        const float e0 = expf(v0 - m), e1 = expf(v1 - m);
        const float e2 = expf(v2 - m), e3 = expf(v3 - m);
        float ssum = e0 + e1 + e2 + e3;
        ssum += __shfl_xor_sync(0xffffffffu, ssum, 1);
        ssum += __shfl_xor_sync(0xffffffffu, ssum, 2);
        const float inv = 0.25f / ssum;
        const bool mk = (mask[row] != 0);
        float2 oa, ob;
        oa.x = mk ? e0 * inv : -2500.0f;
        oa.y = mk ? e1 * inv : -2500.0f;
        ob.x = mk ? e2 * inv : -2500.0f;
        ob.y = mk ? e3 * inv : -2500.0f;
        *(float2*)&g_A[(size_t)row * K_ + 2 * tq]     = oa;
        *(float2*)&g_A[(size_t)row * K_ + 8 + 2 * tq] = ob;
    }
}

// ---------------------------------------------------------------------------
// Kernel 2: ONE CTA per batch, 256 threads. S-softmax with single-exp
// (exp stored in place), then 16x256x256 output GEMM on the tensor pipe.
// ---------------------------------------------------------------------------
__global__ __launch_bounds__(256, 2)
void out_gemm_kernel(const float* __restrict__ tf,
                     float*       __restrict__ out)
{
    extern __shared__ uint32_t smu[];
    const uint32_t sb = smem_u32(smu);
    const int tid  = threadIdx.x;
    const int w    = tid >> 5;          // 0..7
    const int lane = tid & 31;
    const int g    = lane >> 2;
    const int tq   = lane & 3;
    const int b    = blockIdx.x;

    // prefetch X chunk 0: 64 rows x 256 h fp16 = 32KB (2048 16B lines)
    {
        const uint32_t* src = g_Xh + (size_t)(b * S_) * 128;
        #pragma unroll
        for (int j = 0; j < 8; j++) {
            const int line = tid + j * 256;
            const int r = line >> 5, lw = line & 31;
            cpasync16(sb + (uint32_t)(r * XSTW2 + lw * 4) * 4,
                      src + (size_t)r * 128 + lw * 4);
        }
        CP_COMMIT();
    }

    float* Af = (float*)(smu + AF2_OFF);
    float* Tf = (float*)(smu + TF2_OFF);
    float* Ik = (float*)(smu + IK2_OFF);

    for (int idx = tid; idx < S_ * K_; idx += 256) {
        const int s = idx >> 4, k = idx & 15;
        Af[s * AFST + k] = g_A[(size_t)b * S_ * K_ + idx];
    }
    for (int idx = tid; idx < S_; idx += 256)
        Tf[idx] = tf[b * S_ + idx];
    __syncthreads();

    // per-k softmax: warp w handles k = w, w+8. exp computed ONCE, stored.
    #pragma unroll
    for (int kk = 0; kk < 2; kk++) {
        const int k = w + kk * 8;
        float m = -1e30f;
        for (int s = lane; s < S_; s += 32) m = fmaxf(m, Af[s * AFST + k]);
        #pragma unroll
        for (int o = 16; o; o >>= 1) m = fmaxf(m, __shfl_xor_sync(0xffffffffu, m, o));
        float ss = 0.0f;
        for (int s = lane; s < S_; s += 32) {
            const float e = expf(Af[s * AFST + k] - m);
            Af[s * AFST + k] = e;
            ss += e;
        }
        #pragma unroll
        for (int o = 16; o; o >>= 1) ss += __shfl_xor_sync(0xffffffffu, ss, o);
        if (lane == 0) Ik[k] = 1.0f / ss;
    }
    __syncthreads();

    // Ds[k][s] fp16 = Af(exp'd) * Ik * Tf  (no MUFU; s padded to 256)
    for (int idx = tid; idx < 16 * 128; idx += 256) {
        const int k = idx >> 7, sw = idx & 127, s0 = sw * 2;
        const float ik = Ik[k];
        float v0 = 0.0f, v1 = 0.0f;
        if (s0     < S_) v0 = Af[s0 * AFST + k]       * ik * Tf[s0];
        if (s0 + 1 < S_) v1 = Af[(s0 + 1) * AFST + k] * ik * Tf[s0 + 1];
        smu[DS2_OFF + k * DST2 + sw] = pack_h2(v0, v1);
    }

    float acc[4][4];
    #pragma unroll
    for (int n8 = 0; n8 < 4; n8++)
        #pragma unroll
        for (int i = 0; i < 4; i++) acc[n8][i] = 0.0f;

    const int q8 = lane >> 3, r8 = lane & 7;
    const int a_off  = DS2_OFF + ((q8 & 1) * 8 + r8) * DST2 + (q8 >> 1) * 4;
    const int b_srow = (q8 & 1) * 8 + r8;
    const int b_hw   = w * 16 + (q8 >> 1) * 4;   // warp w: h words w*16..+15

    #pragma unroll 1
    for (int c = 0; c < 4; c++) {
        CP_WAIT0();
        __syncthreads();    // chunk c + Ds visible; prior buffer reads done
        if (c < 3) {
            const uint32_t* src = g_Xh + (size_t)(b * S_ + (c + 1) * XCH) * 128;
            const uint32_t dbuf = sb + (uint32_t)(((c + 1) & 1) * XBUF2) * 4;
            #pragma unroll
            for (int j = 0; j < 8; j++) {
                const int line = tid + j * 256;
                const int r = line >> 5, lw = line & 31;
                cpasync16(dbuf + (uint32_t)(r * XSTW2 + lw * 4) * 4,
                          src + (size_t)r * 128 + lw * 4);
            }
            CP_COMMIT();
        }
        const uint32_t xbuf = sb + (uint32_t)((c & 1) * XBUF2) * 4;
        #pragma unroll
        for (int ks = 0; ks < 4; ks++) {
            uint32_t a[4];
            ldsm_x4(a[0], a[1], a[2], a[3],
                    sb + (uint32_t)(a_off + c * 32 + ks * 8) * 4);
            #pragma unroll
            for (int p = 0; p < 2; p++) {
                uint32_t r0, r1, r2, r3;
                ldsm_x4_t(r0, r1, r2, r3,
                    xbuf + (uint32_t)((ks * 16 + b_srow) * XSTW2 + b_hw + p * 8) * 4);
                mma16(acc[2 * p    ], a, r0, r1);
                mma16(acc[2 * p + 1], a, r2, r3);
            }
        }
    }

    // store out[b][k][h]; warp w covers h = w*32 .. +31
    float* ob = out + (size_t)b * K_ * H_;
    #pragma unroll
    for (int n8 = 0; n8 < 4; n8++) {
        const int h = w * 32 + n8 * 8 + 2 * tq;
        *(float2*)&ob[(g    ) * H_ + h] = make_float2(acc[n8][0], acc[n8][1]);
        *(float2*)&ob[(g + 8) * H_ + h] = make_float2(acc[n8][2], acc[n8][3]);
    }
}

// ---------------------------------------------------------------------------
extern "C" void kernel_launch(void* const* d_in, const int* in_sizes, int n_in,
                              void* d_out, int out_size)
{
    const float* X    = (const float*)d_in[0];   // (B,S,H)
    const int*   mask = (const int*)  d_in[1];   // (B,S,1)
    const float* tf   = (const float*)d_in[2];   // (B,S,1)
    const float* W1   = (const float*)d_in[3];
    const float* b1   = (const float*)d_in[4];
    const float* W2   = (const float*)d_in[5];
    const float* b2   = (const float*)d_in[6];
    const float* W3   = (const float*)d_in[7];
    float* out = (float*)d_out;                  // (B,K,H)

    cudaFuncSetAttribute(mlp_softk_kernel,
                         cudaFuncAttributeMaxDynamicSharedMemorySize, SM_BYTES);
    cudaFuncSetAttribute(out_gemm_kernel,
                         cudaFuncAttributeMaxDynamicSharedMemorySize, K2_BYTES);

    void* cnt_ptr = nullptr;
    cudaGetSymbolAddress(&cnt_ptr, g_cnt);
    cudaMemsetAsync(cnt_ptr, 0, sizeof(int));

    prep_kernel<<<466, 256>>>(W1, W2, W3, mask);
    mlp_softk_kernel<<<NBLK, 256, SM_BYTES>>>(X, mask, b1, b2);
    out_gemm_kernel<<<B_, 256, K2_BYTES>>>(tf, out);
}